// round 12
// baseline (speedup 1.0000x reference)
#include <cuda_runtime.h>
#include <math.h>

#define NNODE 20
#define NEDGE 380
#define HID   64
#define NL    3
#define ETILE 64
#define NTILE 6      // ceil(380/64)
#define SH    68     // stride for h-like [20][*] arrays (float4-aligned)
#define SMM   68     // buf edge-major stride (float4 aligned)
#define BLK   256
#define NB    1024

__device__ __forceinline__ float tanh_a(float v){
    float r; asm("tanh.approx.f32 %0, %1;" : "=f"(r) : "f"(v)); return r;
}
__device__ __forceinline__ float silu_f(float v){
    return __fdividef(v, 1.f + __expf(-v));
}
__device__ __forceinline__ float sigm_f(float v){
    return __fdividef(1.f, 1.f + __expf(-v));
}

// packed fp32x2 helpers (sm_103a FFMA2 path — PTX-only)
__device__ __forceinline__ unsigned long long dup2(float v){
    unsigned long long r;
    asm("mov.b64 %0, {%1, %1};" : "=l"(r) : "r"(__float_as_uint(v)));
    return r;
}
__device__ __forceinline__ void ffma2(unsigned long long& acc,
                                      unsigned long long a,
                                      unsigned long long b){
    asm("fma.rn.f32x2 %0, %1, %2, %0;" : "+l"(acc) : "l"(a), "l"(b));
}
__device__ __forceinline__ float2 unpk2(unsigned long long v){
    unsigned int lo, hi;
    asm("mov.b64 {%0, %1}, %2;" : "=r"(lo), "=r"(hi) : "l"(v));
    return make_float2(__uint_as_float(lo), __uint_as_float(hi));
}
__device__ __forceinline__ float hsum2(unsigned long long v){
    float2 p = unpk2(v); return p.x + p.y;
}

// ---- k-paired weight scratch (packed by pack_weights_kernel each launch) ----
// layout: [l][k2][o] ull, low 32 bits = w[2*k2][o], high = w[2*k2+1][o]
__device__ unsigned long long W2p_g[3*2048];
__device__ unsigned long long C1p_g[3*2048];

__global__ void pack_weights_kernel(const float* __restrict__ ew2,
                                    const float* __restrict__ cw1){
    int i = blockIdx.x*blockDim.x + threadIdx.x;
    if (i < 3*2048){
        int l = i >> 11, rem = i & 2047, k2 = rem >> 6, o = rem & 63;
        {
            unsigned int lo = __float_as_uint(ew2[l*4096 + (2*k2)*64 + o]);
            unsigned int hi = __float_as_uint(ew2[l*4096 + (2*k2+1)*64 + o]);
            W2p_g[i] = ((unsigned long long)hi << 32) | (unsigned long long)lo;
        }
        {
            unsigned int lo = __float_as_uint(cw1[l*4096 + (2*k2)*64 + o]);
            unsigned int hi = __float_as_uint(cw1[l*4096 + (2*k2+1)*64 + o]);
            C1p_g[i] = ((unsigned long long)hi << 32) | (unsigned long long)lo;
        }
    }
}

#define SMEM_FLOATS (80 + 4*NNODE*SH + ETILE*SMM + 6*64 + 2*ETILE + 384)

__global__ void __launch_bounds__(BLK, 4)
egnn_critic_kernel(
    const float* __restrict__ obs,   const float* __restrict__ rnn,
    const float* __restrict__ emb_w, const float* __restrict__ emb_b,
    const float* __restrict__ ew1,   const float* __restrict__ eb1,
    const float* __restrict__ ew2,   const float* __restrict__ eb2,
    const float* __restrict__ attw,  const float* __restrict__ attb,
    const float* __restrict__ nw1,   const float* __restrict__ nb1,
    const float* __restrict__ nw2,   const float* __restrict__ nb2,
    const float* __restrict__ cw1,   const float* __restrict__ cb1,
    const float* __restrict__ cw2,
    const float* __restrict__ fc1w,  const float* __restrict__ fc1b,
    const float* __restrict__ fc2w,  const float* __restrict__ fc2b,
    float* __restrict__ out, int copy_rnn)
{
    extern __shared__ float sm[];
    float* x0   = sm;
    float* x1   = x0 + NNODE;
    float* aggx = x1 + NNODE;
    float* aggy = aggx + NNODE;
    float* hS   = aggy + NNODE;          // [20][SH]
    float* hA   = hS + NNODE*SH;
    float* hB   = hA + NNODE*SH;
    float* mag  = hB + NNODE*SH;
    float* buf  = mag + NNODE*SH;        // A1 / Mm edge-major [64][SMM]
    float* w1c  = buf + ETILE*SMM;
    float* b1v  = w1c + 64;
    float* b2v  = b1v + 64;
    float* avv  = b2v + 64;
    float* cb1v = avv + 64;
    float* c2v  = cb1v + 64;
    float* cdx  = c2v + 64;
    float* cdy  = cdx + ETILE;
    short* rS   = (short*)(cdy + ETILE);      // [380]
    short* cS   = rS + 384;                   // [380]

    const int g = blockIdx.x;
    const int t = threadIdx.x;
    const float* ob = obs + g * NNODE * 10;   // EQU+INV = 10 per node

    // ---- edge index tables (per block, once) ----
    for (int e = t; e < NEDGE; e += BLK){
        int r = e / 19, jj = e - 19*r;
        rS[e] = (short)r;
        cS[e] = (short)(jj + (jj >= r));
    }
    // ---- init x, h ----
    if (t < NNODE){ x0[t] = ob[t*10 + 0]; x1[t] = ob[t*10 + 1]; }
    {
        int d = t & 63, ng = t >> 6;
        #pragma unroll
        for (int q = 0; q < 5; ++q){
            int n = ng + 4*q;
            float acc = emb_b[d];
            #pragma unroll
            for (int k = 0; k < 8; ++k) acc += ob[n*10 + 2 + k] * __ldg(emb_w + k*64 + d);
            hS[n*SH + d] = acc;
        }
    }
    __syncthreads();

    for (int l = 0; l < NL; ++l){
        // ---- stage per-layer vectors, zero accumulators ----
        if (t < 64){
            w1c[t]  = ew1[l*129*64 + 128*64 + t];
            b1v[t]  = eb1[l*64 + t];
            b2v[t]  = eb2[l*64 + t];
            avv[t]  = attw[l*64 + t];
            cb1v[t] = cb1[l*64 + t];
            c2v[t]  = cw2[l*64 + t];
        }
        if (t < NNODE){ aggx[t] = 0.f; aggy[t] = 0.f; }
        for (int i = t; i < NNODE*SH; i += BLK) mag[i] = 0.f;
        __syncthreads();

        const float ab = __ldg(attb + l);

        // ---- hA = h @ W1[0:64] + b1 (folded), hB = h @ W1[64:128]
        //      FFMA2 GEMM: half = warps 0-3 (hA) / 4-7 (hB); active ty<5, 4 nodes x 4 outs
        {
            int half = t >> 7;
            int tx = t & 15;
            int ty = (t >> 4) & 7;
            if (ty < 5){
                int n0 = ty, n1 = ty + 5, n2 = ty + 10, n3 = ty + 15;
                unsigned long long acc[4][2];
                #pragma unroll
                for (int i = 0; i < 4; ++i){ acc[i][0] = 0ull; acc[i][1] = 0ull; }
                const ulonglong2* Wg =
                    reinterpret_cast<const ulonglong2*>(ew1 + l*129*64 + half*4096) + tx;
                #pragma unroll 4
                for (int k4 = 0; k4 < 64; k4 += 4){
                    float4 a0 = *(const float4*)(hS + n0*SH + k4);
                    float4 a1 = *(const float4*)(hS + n1*SH + k4);
                    float4 a2 = *(const float4*)(hS + n2*SH + k4);
                    float4 a3 = *(const float4*)(hS + n3*SH + k4);
                    #pragma unroll
                    for (int kk = 0; kk < 4; ++kk){
                        ulonglong2 b = __ldg(Wg + (k4 + kk)*16);
                        unsigned long long d0 = dup2(((float*)&a0)[kk]);
                        unsigned long long d1 = dup2(((float*)&a1)[kk]);
                        unsigned long long d2 = dup2(((float*)&a2)[kk]);
                        unsigned long long d3 = dup2(((float*)&a3)[kk]);
                        ffma2(acc[0][0], d0, b.x); ffma2(acc[0][1], d0, b.y);
                        ffma2(acc[1][0], d1, b.x); ffma2(acc[1][1], d1, b.y);
                        ffma2(acc[2][0], d2, b.x); ffma2(acc[2][1], d2, b.y);
                        ffma2(acc[3][0], d3, b.x); ffma2(acc[3][1], d3, b.y);
                    }
                }
                float* dst = half ? hB : hA;
                float4 bf = half ? make_float4(0.f,0.f,0.f,0.f)
                                 : *(const float4*)(b1v + 4*tx);
                int nn[4] = {n0, n1, n2, n3};
                #pragma unroll
                for (int i = 0; i < 4; ++i){
                    float2 p0 = unpk2(acc[i][0]);
                    float2 p1 = unpk2(acc[i][1]);
                    *(float4*)(dst + nn[i]*SH + 4*tx) =
                        make_float4(p0.x + bf.x, p0.y + bf.y, p1.x + bf.z, p1.y + bf.w);
                }
            }
        }
        __syncthreads();

        const ulonglong2* W2p = reinterpret_cast<const ulonglong2*>(W2p_g + l*2048);
        const ulonglong2* C1p = reinterpret_cast<const ulonglong2*>(C1p_g + l*2048);

        // ---- edge tiles (64 edges) ----
        for (int tile = 0; tile < NTILE; ++tile){
            const int e0 = tile * ETILE;

            // A1 = silu(hA[r] + hB[c] + radial*w1c)  (b1 already in hA)
            {
                int le = t & 63, kg = t >> 6;   // kg: 16 ks each
                int e = e0 + le;
                bool v = (e < NEDGE);
                int r = 0, c = 0; float radial = 0.f;
                if (v){
                    r = rS[e]; c = cS[e];
                    float dx = x0[r] - x0[c], dy = x1[r] - x1[c];
                    radial = dx*dx + dy*dy;
                    if (kg == 0){
                        float inv = 1.f / (sqrtf(radial) + 1e-8f);
                        cdx[le] = dx * inv; cdy[le] = dy * inv;
                    }
                }
                int kbeg = kg * 16;
                #pragma unroll 4
                for (int k4 = kbeg; k4 < kbeg + 16; k4 += 4){
                    float4 o4 = make_float4(0.f, 0.f, 0.f, 0.f);
                    if (v){
                        float4 ha = *(const float4*)(hA + r*SH + k4);
                        float4 hb = *(const float4*)(hB + c*SH + k4);
                        float4 wc = *(const float4*)(w1c + k4);
                        o4.x = silu_f(fmaf(radial, wc.x, ha.x + hb.x));
                        o4.y = silu_f(fmaf(radial, wc.y, ha.y + hb.y));
                        o4.z = silu_f(fmaf(radial, wc.z, ha.z + hb.z));
                        o4.w = silu_f(fmaf(radial, wc.w, ha.w + hb.w));
                    }
                    *(float4*)(buf + le*SMM + k4) = o4;
                }
            }
            __syncthreads();

            // GEMM1 (dup-free k-pair FFMA2): m = silu(A1 @ W2 + b2) * sigmoid(att)
            // epilogue fuses the m_agg segment sum (atomics from registers)
            {
                int tx = t & 15, ty = t >> 4;     // outs 4tx.., edges 4ty..
                unsigned long long acc[4][4];     // [edge][out] k-pair accumulators
                #pragma unroll
                for (int i = 0; i < 4; ++i)
                    #pragma unroll
                    for (int j = 0; j < 4; ++j) acc[i][j] = 0ull;
                #pragma unroll 2
                for (int k4 = 0; k4 < 64; k4 += 4){
                    ulonglong2 a0 = *(const ulonglong2*)(buf + (4*ty+0)*SMM + k4);
                    ulonglong2 a1 = *(const ulonglong2*)(buf + (4*ty+1)*SMM + k4);
                    ulonglong2 a2 = *(const ulonglong2*)(buf + (4*ty+2)*SMM + k4);
                    ulonglong2 a3 = *(const ulonglong2*)(buf + (4*ty+3)*SMM + k4);
                    const ulonglong2* r0 = W2p + (k4 >> 1)*32 + 2*tx;
                    {
                        ulonglong2 w0 = __ldg(r0);
                        ulonglong2 w1 = __ldg(r0 + 1);
                        ffma2(acc[0][0], a0.x, w0.x); ffma2(acc[0][1], a0.x, w0.y);
                        ffma2(acc[0][2], a0.x, w1.x); ffma2(acc[0][3], a0.x, w1.y);
                        ffma2(acc[1][0], a1.x, w0.x); ffma2(acc[1][1], a1.x, w0.y);
                        ffma2(acc[1][2], a1.x, w1.x); ffma2(acc[1][3], a1.x, w1.y);
                        ffma2(acc[2][0], a2.x, w0.x); ffma2(acc[2][1], a2.x, w0.y);
                        ffma2(acc[2][2], a2.x, w1.x); ffma2(acc[2][3], a2.x, w1.y);
                        ffma2(acc[3][0], a3.x, w0.x); ffma2(acc[3][1], a3.x, w0.y);
                        ffma2(acc[3][2], a3.x, w1.x); ffma2(acc[3][3], a3.x, w1.y);
                    }
                    {
                        ulonglong2 w0 = __ldg(r0 + 32);
                        ulonglong2 w1 = __ldg(r0 + 33);
                        ffma2(acc[0][0], a0.y, w0.x); ffma2(acc[0][1], a0.y, w0.y);
                        ffma2(acc[0][2], a0.y, w1.x); ffma2(acc[0][3], a0.y, w1.y);
                        ffma2(acc[1][0], a1.y, w0.x); ffma2(acc[1][1], a1.y, w0.y);
                        ffma2(acc[1][2], a1.y, w1.x); ffma2(acc[1][3], a1.y, w1.y);
                        ffma2(acc[2][0], a2.y, w0.x); ffma2(acc[2][1], a2.y, w0.y);
                        ffma2(acc[2][2], a2.y, w1.x); ffma2(acc[2][3], a2.y, w1.y);
                        ffma2(acc[3][0], a3.y, w0.x); ffma2(acc[3][1], a3.y, w0.y);
                        ffma2(acc[3][2], a3.y, w1.x); ffma2(acc[3][3], a3.y, w1.y);
                    }
                }
                float mz[4][4];
                float attp[4];
                #pragma unroll
                for (int i = 0; i < 4; ++i){
                    float z0 = silu_f(hsum2(acc[i][0]) + b2v[4*tx + 0]);
                    float z1 = silu_f(hsum2(acc[i][1]) + b2v[4*tx + 1]);
                    float z2 = silu_f(hsum2(acc[i][2]) + b2v[4*tx + 2]);
                    float z3 = silu_f(hsum2(acc[i][3]) + b2v[4*tx + 3]);
                    mz[i][0] = z0; mz[i][1] = z1; mz[i][2] = z2; mz[i][3] = z3;
                    attp[i] = z0*avv[4*tx+0] + z1*avv[4*tx+1]
                            + z2*avv[4*tx+2] + z3*avv[4*tx+3];
                }
                #pragma unroll
                for (int m = 8; m >= 1; m >>= 1){
                    #pragma unroll
                    for (int i = 0; i < 4; ++i)
                        attp[i] += __shfl_xor_sync(0xffffffffu, attp[i], m, 16);
                }
                float sg[4];
                #pragma unroll
                for (int i = 0; i < 4; ++i) sg[i] = sigm_f(attp[i] + ab);

                __syncthreads();   // all A1 reads done -> overwrite buf as Mm

                float s0 = 0.f, s1 = 0.f, s2 = 0.f, s3 = 0.f;
                int curr = -1;
                #pragma unroll
                for (int i = 0; i < 4; ++i){
                    float4 mv = make_float4(mz[i][0]*sg[i], mz[i][1]*sg[i],
                                            mz[i][2]*sg[i], mz[i][3]*sg[i]);
                    *(float4*)(buf + (4*ty + i)*SMM + 4*tx) = mv;
                    int e = e0 + 4*ty + i;
                    if (e < NEDGE){
                        int r = rS[e];
                        if (r != curr){
                            if (curr >= 0){
                                atomicAdd(mag + curr*SH + 4*tx + 0, s0);
                                atomicAdd(mag + curr*SH + 4*tx + 1, s1);
                                atomicAdd(mag + curr*SH + 4*tx + 2, s2);
                                atomicAdd(mag + curr*SH + 4*tx + 3, s3);
                            }
                            curr = r; s0 = s1 = s2 = s3 = 0.f;
                        }
                        s0 += mv.x; s1 += mv.y; s2 += mv.z; s3 += mv.w;
                    }
                }
                if (curr >= 0){
                    atomicAdd(mag + curr*SH + 4*tx + 0, s0);
                    atomicAdd(mag + curr*SH + 4*tx + 1, s1);
                    atomicAdd(mag + curr*SH + 4*tx + 2, s2);
                    atomicAdd(mag + curr*SH + 4*tx + 3, s3);
                }
            }
            __syncthreads();

            // GEMM2 (dup-free k-pair FFMA2): t3 = silu(Mm @ cw1 + cb1);
            // w = tanh(t3 @ cw2); scatter coords
            {
                int tx = t & 15, ty = t >> 4;
                unsigned long long acc[4][4];
                #pragma unroll
                for (int i = 0; i < 4; ++i)
                    #pragma unroll
                    for (int j = 0; j < 4; ++j) acc[i][j] = 0ull;
                #pragma unroll 2
                for (int k4 = 0; k4 < 64; k4 += 4){
                    ulonglong2 a0 = *(const ulonglong2*)(buf + (4*ty+0)*SMM + k4);
                    ulonglong2 a1 = *(const ulonglong2*)(buf + (4*ty+1)*SMM + k4);
                    ulonglong2 a2 = *(const ulonglong2*)(buf + (4*ty+2)*SMM + k4);
                    ulonglong2 a3 = *(const ulonglong2*)(buf + (4*ty+3)*SMM + k4);
                    const ulonglong2* r0 = C1p + (k4 >> 1)*32 + 2*tx;
                    {
                        ulonglong2 w0 = __ldg(r0);
                        ulonglong2 w1 = __ldg(r0 + 1);
                        ffma2(acc[0][0], a0.x, w0.x); ffma2(acc[0][1], a0.x, w0.y);
                        ffma2(acc[0][2], a0.x, w1.x); ffma2(acc[0][3], a0.x, w1.y);
                        ffma2(acc[1][0], a1.x, w0.x); ffma2(acc[1][1], a1.x, w0.y);
                        ffma2(acc[1][2], a1.x, w1.x); ffma2(acc[1][3], a1.x, w1.y);
                        ffma2(acc[2][0], a2.x, w0.x); ffma2(acc[2][1], a2.x, w0.y);
                        ffma2(acc[2][2], a2.x, w1.x); ffma2(acc[2][3], a2.x, w1.y);
                        ffma2(acc[3][0], a3.x, w0.x); ffma2(acc[3][1], a3.x, w0.y);
                        ffma2(acc[3][2], a3.x, w1.x); ffma2(acc[3][3], a3.x, w1.y);
                    }
                    {
                        ulonglong2 w0 = __ldg(r0 + 32);
                        ulonglong2 w1 = __ldg(r0 + 33);
                        ffma2(acc[0][0], a0.y, w0.x); ffma2(acc[0][1], a0.y, w0.y);
                        ffma2(acc[0][2], a0.y, w1.x); ffma2(acc[0][3], a0.y, w1.y);
                        ffma2(acc[1][0], a1.y, w0.x); ffma2(acc[1][1], a1.y, w0.y);
                        ffma2(acc[1][2], a1.y, w1.x); ffma2(acc[1][3], a1.y, w1.y);
                        ffma2(acc[2][0], a2.y, w0.x); ffma2(acc[2][1], a2.y, w0.y);
                        ffma2(acc[2][2], a2.y, w1.x); ffma2(acc[2][3], a2.y, w1.y);
                        ffma2(acc[3][0], a3.y, w0.x); ffma2(acc[3][1], a3.y, w0.y);
                        ffma2(acc[3][2], a3.y, w1.x); ffma2(acc[3][3], a3.y, w1.y);
                    }
                }
                float wp[4];
                #pragma unroll
                for (int i = 0; i < 4; ++i){
                    float z0 = silu_f(hsum2(acc[i][0]) + cb1v[4*tx + 0]);
                    float z1 = silu_f(hsum2(acc[i][1]) + cb1v[4*tx + 1]);
                    float z2 = silu_f(hsum2(acc[i][2]) + cb1v[4*tx + 2]);
                    float z3 = silu_f(hsum2(acc[i][3]) + cb1v[4*tx + 3]);
                    wp[i] = z0*c2v[4*tx+0] + z1*c2v[4*tx+1]
                          + z2*c2v[4*tx+2] + z3*c2v[4*tx+3];
                }
                #pragma unroll
                for (int m = 8; m >= 1; m >>= 1){
                    #pragma unroll
                    for (int i = 0; i < 4; ++i)
                        wp[i] += __shfl_xor_sync(0xffffffffu, wp[i], m, 16);
                }
                if (tx == 0){
                    #pragma unroll
                    for (int i = 0; i < 4; ++i){
                        int le = 4*ty + i, e = e0 + le;
                        if (e < NEDGE){
                            float w = tanh_a(wp[i]);
                            int r = rS[e];
                            atomicAdd(aggx + r, cdx[le] * w);
                            atomicAdd(aggy + r, cdy[le] * w);
                        }
                    }
                }
            }
            __syncthreads();   // protects buf/cdx/cdy before next tile
        } // tiles

        // ---- x update (cnt == 19 exactly) ----
        if (t < NNODE){
            x0[t] += aggx[t] * (1.f/19.f);
            x1[t] += aggy[t] * (1.f/19.f);
        }

        // ---- node MLP pass1 (FFMA2): z1 = silu([h,m_agg]@nw1 + nb1) ----
        float* z1 = buf;
        {
            int tx = t & 15, ty = t >> 4;
            if (ty < 10){
                int n0 = ty, n1 = ty + 10;
                unsigned long long acc[2][2];
                acc[0][0]=0ull; acc[0][1]=0ull; acc[1][0]=0ull; acc[1][1]=0ull;
                const ulonglong2* Wg =
                    reinterpret_cast<const ulonglong2*>(nw1 + l*8192) + tx;
                #pragma unroll 4
                for (int k4 = 0; k4 < 64; k4 += 4){
                    float4 a0 = *(const float4*)(hS + n0*SH + k4);
                    float4 a1 = *(const float4*)(hS + n1*SH + k4);
                    #pragma unroll
                    for (int kk = 0; kk < 4; ++kk){
                        ulonglong2 b = __ldg(Wg + (k4 + kk)*16);
                        unsigned long long d0 = dup2(((float*)&a0)[kk]);
                        unsigned long long d1 = dup2(((float*)&a1)[kk]);
                        ffma2(acc[0][0], d0, b.x); ffma2(acc[0][1], d0, b.y);
                        ffma2(acc[1][0], d1, b.x); ffma2(acc[1][1], d1, b.y);
                    }
                }
                #pragma unroll 4
                for (int k4 = 0; k4 < 64; k4 += 4){
                    float4 a0 = *(const float4*)(mag + n0*SH + k4);
                    float4 a1 = *(const float4*)(mag + n1*SH + k4);
                    #pragma unroll
                    for (int kk = 0; kk < 4; ++kk){
                        ulonglong2 b = __ldg(Wg + (64 + k4 + kk)*16);
                        unsigned long long d0 = dup2(((float*)&a0)[kk]);
                        unsigned long long d1 = dup2(((float*)&a1)[kk]);
                        ffma2(acc[0][0], d0, b.x); ffma2(acc[0][1], d0, b.y);
                        ffma2(acc[1][0], d1, b.x); ffma2(acc[1][1], d1, b.y);
                    }
                }
                float4 bb = __ldg(reinterpret_cast<const float4*>(nb1 + l*64) + tx);
                {
                    float2 p0 = unpk2(acc[0][0]), p1 = unpk2(acc[0][1]);
                    *(float4*)(z1 + n0*SH + 4*tx) = make_float4(
                        silu_f(p0.x + bb.x), silu_f(p0.y + bb.y),
                        silu_f(p1.x + bb.z), silu_f(p1.y + bb.w));
                }
                {
                    float2 p0 = unpk2(acc[1][0]), p1 = unpk2(acc[1][1]);
                    *(float4*)(z1 + n1*SH + 4*tx) = make_float4(
                        silu_f(p0.x + bb.x), silu_f(p0.y + bb.y),
                        silu_f(p1.x + bb.z), silu_f(p1.y + bb.w));
                }
            }
        }
        __syncthreads();

        // ---- node MLP pass2 (FFMA2): h += z1 @ nw2 + nb2 ----
        {
            int tx = t & 15, ty = t >> 4;
            if (ty < 10){
                int n0 = ty, n1 = ty + 10;
                unsigned long long acc[2][2];
                acc[0][0]=0ull; acc[0][1]=0ull; acc[1][0]=0ull; acc[1][1]=0ull;
                const ulonglong2* Wg =
                    reinterpret_cast<const ulonglong2*>(nw2 + l*4096) + tx;
                #pragma unroll 4
                for (int k4 = 0; k4 < 64; k4 += 4){
                    float4 a0 = *(const float4*)(z1 + n0*SH + k4);
                    float4 a1 = *(const float4*)(z1 + n1*SH + k4);
                    #pragma unroll
                    for (int kk = 0; kk < 4; ++kk){
                        ulonglong2 b = __ldg(Wg + (k4 + kk)*16);
                        unsigned long long d0 = dup2(((float*)&a0)[kk]);
                        unsigned long long d1 = dup2(((float*)&a1)[kk]);
                        ffma2(acc[0][0], d0, b.x); ffma2(acc[0][1], d0, b.y);
                        ffma2(acc[1][0], d1, b.x); ffma2(acc[1][1], d1, b.y);
                    }
                }
                float4 bb = __ldg(reinterpret_cast<const float4*>(nb2 + l*64) + tx);
                {
                    float2 p0 = unpk2(acc[0][0]), p1 = unpk2(acc[0][1]);
                    float4 h0 = *(const float4*)(hS + n0*SH + 4*tx);
                    h0.x += p0.x + bb.x; h0.y += p0.y + bb.y;
                    h0.z += p1.x + bb.z; h0.w += p1.y + bb.w;
                    *(float4*)(hS + n0*SH + 4*tx) = h0;
                }
                {
                    float2 p0 = unpk2(acc[1][0]), p1 = unpk2(acc[1][1]);
                    float4 h1 = *(const float4*)(hS + n1*SH + 4*tx);
                    h1.x += p0.x + bb.x; h1.y += p0.y + bb.y;
                    h1.z += p1.x + bb.z; h1.w += p1.y + bb.w;
                    *(float4*)(hS + n1*SH + 4*tx) = h1;
                }
            }
        }
        __syncthreads();
    } // layers

    // ---- value head (FFMA2): z1 = tanh([xsq,h] @ fc1w + fc1b) ----
    float* z1 = buf;
    {
        int tx = t & 15, ty = t >> 4;
        if (ty < 10){
            int n0 = ty, n1 = ty + 10;
            unsigned long long acc[2][2];
            acc[0][0]=0ull; acc[0][1]=0ull; acc[1][0]=0ull; acc[1][1]=0ull;
            const ulonglong2* Wg =
                reinterpret_cast<const ulonglong2*>(fc1w + 64) + tx;   // rows 1..64
            #pragma unroll 4
            for (int k4 = 0; k4 < 64; k4 += 4){
                float4 a0 = *(const float4*)(hS + n0*SH + k4);
                float4 a1 = *(const float4*)(hS + n1*SH + k4);
                #pragma unroll
                for (int kk = 0; kk < 4; ++kk){
                    ulonglong2 b = __ldg(Wg + (k4 + kk)*16);
                    unsigned long long d0 = dup2(((float*)&a0)[kk]);
                    unsigned long long d1 = dup2(((float*)&a1)[kk]);
                    ffma2(acc[0][0], d0, b.x); ffma2(acc[0][1], d0, b.y);
                    ffma2(acc[1][0], d1, b.x); ffma2(acc[1][1], d1, b.y);
                }
            }
            float4 w0 = __ldg(reinterpret_cast<const float4*>(fc1w) + tx);  // xsq row
            float4 bb = __ldg(reinterpret_cast<const float4*>(fc1b) + tx);
            float xsq0 = x0[n0]*x0[n0] + x1[n0]*x1[n0];
            float xsq1 = x0[n1]*x0[n1] + x1[n1]*x1[n1];
            {
                float2 p0 = unpk2(acc[0][0]), p1 = unpk2(acc[0][1]);
                *(float4*)(z1 + n0*SH + 4*tx) = make_float4(
                    tanh_a(fmaf(xsq0, w0.x, p0.x + bb.x)),
                    tanh_a(fmaf(xsq0, w0.y, p0.y + bb.y)),
                    tanh_a(fmaf(xsq0, w0.z, p1.x + bb.z)),
                    tanh_a(fmaf(xsq0, w0.w, p1.y + bb.w)));
            }
            {
                float2 p0 = unpk2(acc[1][0]), p1 = unpk2(acc[1][1]);
                *(float4*)(z1 + n1*SH + 4*tx) = make_float4(
                    tanh_a(fmaf(xsq1, w0.x, p0.x + bb.x)),
                    tanh_a(fmaf(xsq1, w0.y, p0.y + bb.y)),
                    tanh_a(fmaf(xsq1, w0.z, p1.x + bb.z)),
                    tanh_a(fmaf(xsq1, w0.w, p1.y + bb.w)));
            }
        }
    }
    __syncthreads();
    if (t < 32){
        float v = 0.f;
        if (t < NNODE){
            v = __ldg(fc2b);
            #pragma unroll 4
            for (int k4 = 0; k4 < 64; k4 += 4){
                float4 z = *(const float4*)(z1 + t*SH + k4);
                float4 w = *(const float4*)(fc2w + k4);
                v = fmaf(z.x, w.x, v); v = fmaf(z.y, w.y, v);
                v = fmaf(z.z, w.z, v); v = fmaf(z.w, w.w, v);
            }
        }
        #pragma unroll
        for (int m = 16; m >= 1; m >>= 1) v += __shfl_xor_sync(0xffffffffu, v, m);
        if (t == 0) out[g] = v * (1.f / NNODE);
    }
    // rnn_states passthrough
    if (copy_rnn && t < 64) out[NB + g*64 + t] = rnn[g*64 + t];
}

extern "C" void kernel_launch(void* const* d_in, const int* in_sizes, int n_in,
                              void* d_out, int out_size)
{
    const float* obs   = (const float*)d_in[0];
    const float* rnn   = (const float*)d_in[1];
    // d_in[2] = masks (unused)
    const float* emb_w = (const float*)d_in[3];
    const float* emb_b = (const float*)d_in[4];
    const float* ew1   = (const float*)d_in[5];
    const float* eb1   = (const float*)d_in[6];
    const float* ew2   = (const float*)d_in[7];
    const float* eb2   = (const float*)d_in[8];
    const float* attw  = (const float*)d_in[9];
    const float* attb  = (const float*)d_in[10];
    const float* nw1   = (const float*)d_in[11];
    const float* nb1   = (const float*)d_in[12];
    const float* nw2   = (const float*)d_in[13];
    const float* nb2   = (const float*)d_in[14];
    const float* cw1   = (const float*)d_in[15];
    const float* cb1   = (const float*)d_in[16];
    const float* cw2   = (const float*)d_in[17];
    const float* fc1w  = (const float*)d_in[18];
    const float* fc1b  = (const float*)d_in[19];
    const float* fc2w  = (const float*)d_in[20];
    const float* fc2b  = (const float*)d_in[21];
    // d_in[22], d_in[23] = edge_row/edge_col (recomputed analytically)

    // pack k-paired weight copies (graph-capturable: plain kernel launch)
    pack_weights_kernel<<<24, 256>>>(ew2, cw1);

    const size_t smem_bytes = (size_t)SMEM_FLOATS * sizeof(float);
    cudaFuncSetAttribute(egnn_critic_kernel,
                         cudaFuncAttributeMaxDynamicSharedMemorySize,
                         (int)smem_bytes);

    int copy_rnn = (out_size >= NB + NB*HID) ? 1 : 0;

    egnn_critic_kernel<<<NB, BLK, smem_bytes>>>(
        obs, rnn, emb_w, emb_b, ew1, eb1, ew2, eb2, attw, attb,
        nw1, nb1, nw2, nb2, cw1, cb1, cw2, fc1w, fc1b, fc2w, fc2b,
        (float*)d_out, copy_rnn);
}

// round 13
// speedup vs baseline: 1.3752x; 1.3752x over previous
#include <cuda_runtime.h>
#include <math.h>

#define NNODE 20
#define NEDGE 380
#define HID   64
#define NL    3
#define ETILE 64
#define NTILE 6      // ceil(380/64)
#define SH    68     // stride for h-like [20][*] arrays (float4-aligned)
#define SMM   68     // buf edge-major stride (float4 aligned)
#define BLK   256
#define NB    1024

__device__ __forceinline__ float tanh_a(float v){
    float r; asm("tanh.approx.f32 %0, %1;" : "=f"(r) : "f"(v)); return r;
}
__device__ __forceinline__ float silu_f(float v){
    return __fdividef(v, 1.f + __expf(-v));
}
__device__ __forceinline__ float sigm_f(float v){
    return __fdividef(1.f, 1.f + __expf(-v));
}

// packed fp32x2 helpers (sm_103a FFMA2 path — PTX-only)
__device__ __forceinline__ unsigned long long dup2(float v){
    unsigned long long r;
    asm("mov.b64 %0, {%1, %1};" : "=l"(r) : "r"(__float_as_uint(v)));
    return r;
}
__device__ __forceinline__ void ffma2(unsigned long long& acc,
                                      unsigned long long a,
                                      unsigned long long b){
    asm("fma.rn.f32x2 %0, %1, %2, %0;" : "+l"(acc) : "l"(a), "l"(b));
}
__device__ __forceinline__ float2 unpk2(unsigned long long v){
    unsigned int lo, hi;
    asm("mov.b64 {%0, %1}, %2;" : "=r"(lo), "=r"(hi) : "l"(v));
    return make_float2(__uint_as_float(lo), __uint_as_float(hi));
}

#define SMEM_FLOATS (80 + 4*NNODE*SH + ETILE*SMM + 6*64 + 2*ETILE + 384)

__global__ void __launch_bounds__(BLK, 4)
egnn_critic_kernel(
    const float* __restrict__ obs,   const float* __restrict__ rnn,
    const float* __restrict__ emb_w, const float* __restrict__ emb_b,
    const float* __restrict__ ew1,   const float* __restrict__ eb1,
    const float* __restrict__ ew2,   const float* __restrict__ eb2,
    const float* __restrict__ attw,  const float* __restrict__ attb,
    const float* __restrict__ nw1,   const float* __restrict__ nb1,
    const float* __restrict__ nw2,   const float* __restrict__ nb2,
    const float* __restrict__ cw1,   const float* __restrict__ cb1,
    const float* __restrict__ cw2,
    const float* __restrict__ fc1w,  const float* __restrict__ fc1b,
    const float* __restrict__ fc2w,  const float* __restrict__ fc2b,
    float* __restrict__ out, int copy_rnn)
{
    extern __shared__ float sm[];
    float* x0   = sm;
    float* x1   = x0 + NNODE;
    float* aggx = x1 + NNODE;
    float* aggy = aggx + NNODE;
    float* hS   = aggy + NNODE;          // [20][SH]
    float* hA   = hS + NNODE*SH;
    float* hB   = hA + NNODE*SH;
    float* mag  = hB + NNODE*SH;
    float* buf  = mag + NNODE*SH;        // A1 / Mm edge-major [64][SMM]
    float* w1c  = buf + ETILE*SMM;
    float* b1v  = w1c + 64;
    float* b2v  = b1v + 64;
    float* avv  = b2v + 64;
    float* cb1v = avv + 64;
    float* c2v  = cb1v + 64;
    float* cdx  = c2v + 64;
    float* cdy  = cdx + ETILE;
    short* rS   = (short*)(cdy + ETILE);      // [380]
    short* cS   = rS + 384;                   // [380]

    const int g = blockIdx.x;
    const int t = threadIdx.x;
    const float* ob = obs + g * NNODE * 10;   // EQU+INV = 10 per node

    // ---- edge index tables (per block, once) ----
    for (int e = t; e < NEDGE; e += BLK){
        int r = e / 19, jj = e - 19*r;
        rS[e] = (short)r;
        cS[e] = (short)(jj + (jj >= r));
    }
    // ---- init x, h ----
    if (t < NNODE){ x0[t] = ob[t*10 + 0]; x1[t] = ob[t*10 + 1]; }
    {
        int d = t & 63, ng = t >> 6;
        #pragma unroll
        for (int q = 0; q < 5; ++q){
            int n = ng + 4*q;
            float acc = emb_b[d];
            #pragma unroll
            for (int k = 0; k < 8; ++k) acc += ob[n*10 + 2 + k] * __ldg(emb_w + k*64 + d);
            hS[n*SH + d] = acc;
        }
    }
    __syncthreads();

    for (int l = 0; l < NL; ++l){
        // ---- stage per-layer vectors, zero accumulators ----
        if (t < 64){
            w1c[t]  = ew1[l*129*64 + 128*64 + t];
            b1v[t]  = eb1[l*64 + t];
            b2v[t]  = eb2[l*64 + t];
            avv[t]  = attw[l*64 + t];
            cb1v[t] = cb1[l*64 + t];
            c2v[t]  = cw2[l*64 + t];
        }
        if (t < NNODE){ aggx[t] = 0.f; aggy[t] = 0.f; }
        for (int i = t; i < NNODE*SH; i += BLK) mag[i] = 0.f;
        __syncthreads();

        const float ab = __ldg(attb + l);

        // ---- hA = h @ W1[0:64] + b1 (folded), hB = h @ W1[64:128]
        //      FFMA2 GEMM: half = warps 0-3 (hA) / 4-7 (hB); active ty<5, 4 nodes x 4 outs
        {
            int half = t >> 7;
            int tx = t & 15;
            int ty = (t >> 4) & 7;
            if (ty < 5){
                int n0 = ty, n1 = ty + 5, n2 = ty + 10, n3 = ty + 15;
                unsigned long long acc[4][2];
                #pragma unroll
                for (int i = 0; i < 4; ++i){ acc[i][0] = 0ull; acc[i][1] = 0ull; }
                const ulonglong2* Wg =
                    reinterpret_cast<const ulonglong2*>(ew1 + l*129*64 + half*4096) + tx;
                #pragma unroll 4
                for (int k4 = 0; k4 < 64; k4 += 4){
                    float4 a0 = *(const float4*)(hS + n0*SH + k4);
                    float4 a1 = *(const float4*)(hS + n1*SH + k4);
                    float4 a2 = *(const float4*)(hS + n2*SH + k4);
                    float4 a3 = *(const float4*)(hS + n3*SH + k4);
                    #pragma unroll
                    for (int kk = 0; kk < 4; ++kk){
                        ulonglong2 b = __ldg(Wg + (k4 + kk)*16);
                        unsigned long long d0 = dup2(((float*)&a0)[kk]);
                        unsigned long long d1 = dup2(((float*)&a1)[kk]);
                        unsigned long long d2 = dup2(((float*)&a2)[kk]);
                        unsigned long long d3 = dup2(((float*)&a3)[kk]);
                        ffma2(acc[0][0], d0, b.x); ffma2(acc[0][1], d0, b.y);
                        ffma2(acc[1][0], d1, b.x); ffma2(acc[1][1], d1, b.y);
                        ffma2(acc[2][0], d2, b.x); ffma2(acc[2][1], d2, b.y);
                        ffma2(acc[3][0], d3, b.x); ffma2(acc[3][1], d3, b.y);
                    }
                }
                float* dst = half ? hB : hA;
                float4 bf = half ? make_float4(0.f,0.f,0.f,0.f)
                                 : *(const float4*)(b1v + 4*tx);
                int nn[4] = {n0, n1, n2, n3};
                #pragma unroll
                for (int i = 0; i < 4; ++i){
                    float2 p0 = unpk2(acc[i][0]);
                    float2 p1 = unpk2(acc[i][1]);
                    *(float4*)(dst + nn[i]*SH + 4*tx) =
                        make_float4(p0.x + bf.x, p0.y + bf.y, p1.x + bf.z, p1.y + bf.w);
                }
            }
        }
        __syncthreads();

        const ulonglong2* W2g = reinterpret_cast<const ulonglong2*>(ew2 + l*4096);
        const ulonglong2* C1g = reinterpret_cast<const ulonglong2*>(cw1 + l*4096);

        // ---- edge tiles (64 edges) ----
        for (int tile = 0; tile < NTILE; ++tile){
            const int e0 = tile * ETILE;

            // A1 = silu(hA[r] + hB[c] + radial*w1c)  (b1 already in hA)
            {
                int le = t & 63, kg = t >> 6;   // kg: 16 ks each
                int e = e0 + le;
                bool v = (e < NEDGE);
                int r = 0, c = 0; float radial = 0.f;
                if (v){
                    r = rS[e]; c = cS[e];
                    float dx = x0[r] - x0[c], dy = x1[r] - x1[c];
                    radial = dx*dx + dy*dy;
                    if (kg == 0){
                        float inv = 1.f / (sqrtf(radial) + 1e-8f);
                        cdx[le] = dx * inv; cdy[le] = dy * inv;
                    }
                }
                int kbeg = kg * 16;
                #pragma unroll 4
                for (int k4 = kbeg; k4 < kbeg + 16; k4 += 4){
                    float4 o4 = make_float4(0.f, 0.f, 0.f, 0.f);
                    if (v){
                        float4 ha = *(const float4*)(hA + r*SH + k4);
                        float4 hb = *(const float4*)(hB + c*SH + k4);
                        float4 wc = *(const float4*)(w1c + k4);
                        o4.x = silu_f(fmaf(radial, wc.x, ha.x + hb.x));
                        o4.y = silu_f(fmaf(radial, wc.y, ha.y + hb.y));
                        o4.z = silu_f(fmaf(radial, wc.z, ha.z + hb.z));
                        o4.w = silu_f(fmaf(radial, wc.w, ha.w + hb.w));
                    }
                    *(float4*)(buf + le*SMM + k4) = o4;
                }
            }
            __syncthreads();

            // GEMM1 (FFMA2, unroll 8): m = silu(A1 @ W2 + b2) gated by sigmoid(att)
            // epilogue fuses the m_agg segment sum (atomics from registers)
            {
                int tx = t & 15, ty = t >> 4;     // outs 4tx.., edges 4ty..
                unsigned long long acc[4][2];     // [edge][out-pair]
                #pragma unroll
                for (int i = 0; i < 4; ++i){ acc[i][0] = 0ull; acc[i][1] = 0ull; }
                const ulonglong2* Bp = W2g + tx;
                #pragma unroll 8
                for (int k4 = 0; k4 < 64; k4 += 4){
                    float4 a0 = *(const float4*)(buf + (4*ty+0)*SMM + k4);
                    float4 a1 = *(const float4*)(buf + (4*ty+1)*SMM + k4);
                    float4 a2 = *(const float4*)(buf + (4*ty+2)*SMM + k4);
                    float4 a3 = *(const float4*)(buf + (4*ty+3)*SMM + k4);
                    #pragma unroll
                    for (int kk = 0; kk < 4; ++kk){
                        ulonglong2 b = __ldg(Bp + (k4 + kk)*16);
                        unsigned long long d0 = dup2(((float*)&a0)[kk]);
                        unsigned long long d1 = dup2(((float*)&a1)[kk]);
                        unsigned long long d2 = dup2(((float*)&a2)[kk]);
                        unsigned long long d3 = dup2(((float*)&a3)[kk]);
                        ffma2(acc[0][0], d0, b.x); ffma2(acc[0][1], d0, b.y);
                        ffma2(acc[1][0], d1, b.x); ffma2(acc[1][1], d1, b.y);
                        ffma2(acc[2][0], d2, b.x); ffma2(acc[2][1], d2, b.y);
                        ffma2(acc[3][0], d3, b.x); ffma2(acc[3][1], d3, b.y);
                    }
                }
                float mz[4][4];
                float attp[4];
                #pragma unroll
                for (int i = 0; i < 4; ++i){
                    float2 p0 = unpk2(acc[i][0]);
                    float2 p1 = unpk2(acc[i][1]);
                    float z0 = silu_f(p0.x + b2v[4*tx + 0]);
                    float z1 = silu_f(p0.y + b2v[4*tx + 1]);
                    float z2 = silu_f(p1.x + b2v[4*tx + 2]);
                    float z3 = silu_f(p1.y + b2v[4*tx + 3]);
                    mz[i][0] = z0; mz[i][1] = z1; mz[i][2] = z2; mz[i][3] = z3;
                    attp[i] = z0*avv[4*tx+0] + z1*avv[4*tx+1]
                            + z2*avv[4*tx+2] + z3*avv[4*tx+3];
                }
                #pragma unroll
                for (int m = 8; m >= 1; m >>= 1){
                    #pragma unroll
                    for (int i = 0; i < 4; ++i)
                        attp[i] += __shfl_xor_sync(0xffffffffu, attp[i], m, 16);
                }
                float sg[4];
                #pragma unroll
                for (int i = 0; i < 4; ++i) sg[i] = sigm_f(attp[i] + ab);

                __syncthreads();   // all A1 reads done -> overwrite buf as Mm

                float s0 = 0.f, s1 = 0.f, s2 = 0.f, s3 = 0.f;
                int curr = -1;
                #pragma unroll
                for (int i = 0; i < 4; ++i){
                    float4 mv = make_float4(mz[i][0]*sg[i], mz[i][1]*sg[i],
                                            mz[i][2]*sg[i], mz[i][3]*sg[i]);
                    *(float4*)(buf + (4*ty + i)*SMM + 4*tx) = mv;
                    int e = e0 + 4*ty + i;
                    if (e < NEDGE){
                        int r = rS[e];
                        if (r != curr){
                            if (curr >= 0){
                                atomicAdd(mag + curr*SH + 4*tx + 0, s0);
                                atomicAdd(mag + curr*SH + 4*tx + 1, s1);
                                atomicAdd(mag + curr*SH + 4*tx + 2, s2);
                                atomicAdd(mag + curr*SH + 4*tx + 3, s3);
                            }
                            curr = r; s0 = s1 = s2 = s3 = 0.f;
                        }
                        s0 += mv.x; s1 += mv.y; s2 += mv.z; s3 += mv.w;
                    }
                }
                if (curr >= 0){
                    atomicAdd(mag + curr*SH + 4*tx + 0, s0);
                    atomicAdd(mag + curr*SH + 4*tx + 1, s1);
                    atomicAdd(mag + curr*SH + 4*tx + 2, s2);
                    atomicAdd(mag + curr*SH + 4*tx + 3, s3);
                }
            }
            __syncthreads();

            // GEMM2 (FFMA2, unroll 8): t3 = silu(Mm @ cw1 + cb1); w = tanh(t3 @ cw2)
            {
                int tx = t & 15, ty = t >> 4;
                unsigned long long acc[4][2];
                #pragma unroll
                for (int i = 0; i < 4; ++i){ acc[i][0] = 0ull; acc[i][1] = 0ull; }
                const ulonglong2* Bp = C1g + tx;
                #pragma unroll 8
                for (int k4 = 0; k4 < 64; k4 += 4){
                    float4 a0 = *(const float4*)(buf + (4*ty+0)*SMM + k4);
                    float4 a1 = *(const float4*)(buf + (4*ty+1)*SMM + k4);
                    float4 a2 = *(const float4*)(buf + (4*ty+2)*SMM + k4);
                    float4 a3 = *(const float4*)(buf + (4*ty+3)*SMM + k4);
                    #pragma unroll
                    for (int kk = 0; kk < 4; ++kk){
                        ulonglong2 b = __ldg(Bp + (k4 + kk)*16);
                        unsigned long long d0 = dup2(((float*)&a0)[kk]);
                        unsigned long long d1 = dup2(((float*)&a1)[kk]);
                        unsigned long long d2 = dup2(((float*)&a2)[kk]);
                        unsigned long long d3 = dup2(((float*)&a3)[kk]);
                        ffma2(acc[0][0], d0, b.x); ffma2(acc[0][1], d0, b.y);
                        ffma2(acc[1][0], d1, b.x); ffma2(acc[1][1], d1, b.y);
                        ffma2(acc[2][0], d2, b.x); ffma2(acc[2][1], d2, b.y);
                        ffma2(acc[3][0], d3, b.x); ffma2(acc[3][1], d3, b.y);
                    }
                }
                float wp[4];
                #pragma unroll
                for (int i = 0; i < 4; ++i){
                    float2 p0 = unpk2(acc[i][0]);
                    float2 p1 = unpk2(acc[i][1]);
                    float z0 = silu_f(p0.x + cb1v[4*tx + 0]);
                    float z1 = silu_f(p0.y + cb1v[4*tx + 1]);
                    float z2 = silu_f(p1.x + cb1v[4*tx + 2]);
                    float z3 = silu_f(p1.y + cb1v[4*tx + 3]);
                    wp[i] = z0*c2v[4*tx+0] + z1*c2v[4*tx+1]
                          + z2*c2v[4*tx+2] + z3*c2v[4*tx+3];
                }
                #pragma unroll
                for (int m = 8; m >= 1; m >>= 1){
                    #pragma unroll
                    for (int i = 0; i < 4; ++i)
                        wp[i] += __shfl_xor_sync(0xffffffffu, wp[i], m, 16);
                }
                if (tx == 0){
                    #pragma unroll
                    for (int i = 0; i < 4; ++i){
                        int le = 4*ty + i, e = e0 + le;
                        if (e < NEDGE){
                            float w = tanh_a(wp[i]);
                            int r = rS[e];
                            atomicAdd(aggx + r, cdx[le] * w);
                            atomicAdd(aggy + r, cdy[le] * w);
                        }
                    }
                }
            }
            __syncthreads();   // protects buf/cdx/cdy before next tile
        } // tiles

        // ---- x update (cnt == 19 exactly) ----
        if (t < NNODE){
            x0[t] += aggx[t] * (1.f/19.f);
            x1[t] += aggy[t] * (1.f/19.f);
        }

        // ---- node MLP pass1 (FFMA2): z1 = silu([h,m_agg]@nw1 + nb1) ----
        float* z1 = buf;
        {
            int tx = t & 15, ty = t >> 4;
            if (ty < 10){
                int n0 = ty, n1 = ty + 10;
                unsigned long long acc[2][2];
                acc[0][0]=0ull; acc[0][1]=0ull; acc[1][0]=0ull; acc[1][1]=0ull;
                const ulonglong2* Wg =
                    reinterpret_cast<const ulonglong2*>(nw1 + l*8192) + tx;
                #pragma unroll 4
                for (int k4 = 0; k4 < 64; k4 += 4){
                    float4 a0 = *(const float4*)(hS + n0*SH + k4);
                    float4 a1 = *(const float4*)(hS + n1*SH + k4);
                    #pragma unroll
                    for (int kk = 0; kk < 4; ++kk){
                        ulonglong2 b = __ldg(Wg + (k4 + kk)*16);
                        unsigned long long d0 = dup2(((float*)&a0)[kk]);
                        unsigned long long d1 = dup2(((float*)&a1)[kk]);
                        ffma2(acc[0][0], d0, b.x); ffma2(acc[0][1], d0, b.y);
                        ffma2(acc[1][0], d1, b.x); ffma2(acc[1][1], d1, b.y);
                    }
                }
                #pragma unroll 4
                for (int k4 = 0; k4 < 64; k4 += 4){
                    float4 a0 = *(const float4*)(mag + n0*SH + k4);
                    float4 a1 = *(const float4*)(mag + n1*SH + k4);
                    #pragma unroll
                    for (int kk = 0; kk < 4; ++kk){
                        ulonglong2 b = __ldg(Wg + (64 + k4 + kk)*16);
                        unsigned long long d0 = dup2(((float*)&a0)[kk]);
                        unsigned long long d1 = dup2(((float*)&a1)[kk]);
                        ffma2(acc[0][0], d0, b.x); ffma2(acc[0][1], d0, b.y);
                        ffma2(acc[1][0], d1, b.x); ffma2(acc[1][1], d1, b.y);
                    }
                }
                float4 bb = __ldg(reinterpret_cast<const float4*>(nb1 + l*64) + tx);
                {
                    float2 p0 = unpk2(acc[0][0]), p1 = unpk2(acc[0][1]);
                    *(float4*)(z1 + n0*SH + 4*tx) = make_float4(
                        silu_f(p0.x + bb.x), silu_f(p0.y + bb.y),
                        silu_f(p1.x + bb.z), silu_f(p1.y + bb.w));
                }
                {
                    float2 p0 = unpk2(acc[1][0]), p1 = unpk2(acc[1][1]);
                    *(float4*)(z1 + n1*SH + 4*tx) = make_float4(
                        silu_f(p0.x + bb.x), silu_f(p0.y + bb.y),
                        silu_f(p1.x + bb.z), silu_f(p1.y + bb.w));
                }
            }
        }
        __syncthreads();

        // ---- node MLP pass2 (FFMA2): h += z1 @ nw2 + nb2 ----
        {
            int tx = t & 15, ty = t >> 4;
            if (ty < 10){
                int n0 = ty, n1 = ty + 10;
                unsigned long long acc[2][2];
                acc[0][0]=0ull; acc[0][1]=0ull; acc[1][0]=0ull; acc[1][1]=0ull;
                const ulonglong2* Wg =
                    reinterpret_cast<const ulonglong2*>(nw2 + l*4096) + tx;
                #pragma unroll 4
                for (int k4 = 0; k4 < 64; k4 += 4){
                    float4 a0 = *(const float4*)(z1 + n0*SH + k4);
                    float4 a1 = *(const float4*)(z1 + n1*SH + k4);
                    #pragma unroll
                    for (int kk = 0; kk < 4; ++kk){
                        ulonglong2 b = __ldg(Wg + (k4 + kk)*16);
                        unsigned long long d0 = dup2(((float*)&a0)[kk]);
                        unsigned long long d1 = dup2(((float*)&a1)[kk]);
                        ffma2(acc[0][0], d0, b.x); ffma2(acc[0][1], d0, b.y);
                        ffma2(acc[1][0], d1, b.x); ffma2(acc[1][1], d1, b.y);
                    }
                }
                float4 bb = __ldg(reinterpret_cast<const float4*>(nb2 + l*64) + tx);
                {
                    float2 p0 = unpk2(acc[0][0]), p1 = unpk2(acc[0][1]);
                    float4 h0 = *(const float4*)(hS + n0*SH + 4*tx);
                    h0.x += p0.x + bb.x; h0.y += p0.y + bb.y;
                    h0.z += p1.x + bb.z; h0.w += p1.y + bb.w;
                    *(float4*)(hS + n0*SH + 4*tx) = h0;
                }
                {
                    float2 p0 = unpk2(acc[1][0]), p1 = unpk2(acc[1][1]);
                    float4 h1 = *(const float4*)(hS + n1*SH + 4*tx);
                    h1.x += p0.x + bb.x; h1.y += p0.y + bb.y;
                    h1.z += p1.x + bb.z; h1.w += p1.y + bb.w;
                    *(float4*)(hS + n1*SH + 4*tx) = h1;
                }
            }
        }
        __syncthreads();
    } // layers

    // ---- value head (FFMA2): z1 = tanh([xsq,h] @ fc1w + fc1b) ----
    float* z1 = buf;
    {
        int tx = t & 15, ty = t >> 4;
        if (ty < 10){
            int n0 = ty, n1 = ty + 10;
            unsigned long long acc[2][2];
            acc[0][0]=0ull; acc[0][1]=0ull; acc[1][0]=0ull; acc[1][1]=0ull;
            const ulonglong2* Wg =
                reinterpret_cast<const ulonglong2*>(fc1w + 64) + tx;   // rows 1..64
            #pragma unroll 4
            for (int k4 = 0; k4 < 64; k4 += 4){
                float4 a0 = *(const float4*)(hS + n0*SH + k4);
                float4 a1 = *(const float4*)(hS + n1*SH + k4);
                #pragma unroll
                for (int kk = 0; kk < 4; ++kk){
                    ulonglong2 b = __ldg(Wg + (k4 + kk)*16);
                    unsigned long long d0 = dup2(((float*)&a0)[kk]);
                    unsigned long long d1 = dup2(((float*)&a1)[kk]);
                    ffma2(acc[0][0], d0, b.x); ffma2(acc[0][1], d0, b.y);
                    ffma2(acc[1][0], d1, b.x); ffma2(acc[1][1], d1, b.y);
                }
            }
            float4 w0 = __ldg(reinterpret_cast<const float4*>(fc1w) + tx);  // xsq row
            float4 bb = __ldg(reinterpret_cast<const float4*>(fc1b) + tx);
            float xsq0 = x0[n0]*x0[n0] + x1[n0]*x1[n0];
            float xsq1 = x0[n1]*x0[n1] + x1[n1]*x1[n1];
            {
                float2 p0 = unpk2(acc[0][0]), p1 = unpk2(acc[0][1]);
                *(float4*)(z1 + n0*SH + 4*tx) = make_float4(
                    tanh_a(fmaf(xsq0, w0.x, p0.x + bb.x)),
                    tanh_a(fmaf(xsq0, w0.y, p0.y + bb.y)),
                    tanh_a(fmaf(xsq0, w0.z, p1.x + bb.z)),
                    tanh_a(fmaf(xsq0, w0.w, p1.y + bb.w)));
            }
            {
                float2 p0 = unpk2(acc[1][0]), p1 = unpk2(acc[1][1]);
                *(float4*)(z1 + n1*SH + 4*tx) = make_float4(
                    tanh_a(fmaf(xsq1, w0.x, p0.x + bb.x)),
                    tanh_a(fmaf(xsq1, w0.y, p0.y + bb.y)),
                    tanh_a(fmaf(xsq1, w0.z, p1.x + bb.z)),
                    tanh_a(fmaf(xsq1, w0.w, p1.y + bb.w)));
            }
        }
    }
    __syncthreads();
    if (t < 32){
        float v = 0.f;
        if (t < NNODE){
            v = __ldg(fc2b);
            #pragma unroll 4
            for (int k4 = 0; k4 < 64; k4 += 4){
                float4 z = *(const float4*)(z1 + t*SH + k4);
                float4 w = *(const float4*)(fc2w + k4);
                v = fmaf(z.x, w.x, v); v = fmaf(z.y, w.y, v);
                v = fmaf(z.z, w.z, v); v = fmaf(z.w, w.w, v);
            }
        }
        #pragma unroll
        for (int m = 16; m >= 1; m >>= 1) v += __shfl_xor_sync(0xffffffffu, v, m);
        if (t == 0) out[g] = v * (1.f / NNODE);
    }
    // rnn_states passthrough
    if (copy_rnn && t < 64) out[NB + g*64 + t] = rnn[g*64 + t];
}

extern "C" void kernel_launch(void* const* d_in, const int* in_sizes, int n_in,
                              void* d_out, int out_size)
{
    const float* obs   = (const float*)d_in[0];
    const float* rnn   = (const float*)d_in[1];
    // d_in[2] = masks (unused)
    const float* emb_w = (const float*)d_in[3];
    const float* emb_b = (const float*)d_in[4];
    const float* ew1   = (const float*)d_in[5];
    const float* eb1   = (const float*)d_in[6];
    const float* ew2   = (const float*)d_in[7];
    const float* eb2   = (const float*)d_in[8];
    const float* attw  = (const float*)d_in[9];
    const float* attb  = (const float*)d_in[10];
    const float* nw1   = (const float*)d_in[11];
    const float* nb1   = (const float*)d_in[12];
    const float* nw2   = (const float*)d_in[13];
    const float* nb2   = (const float*)d_in[14];
    const float* cw1   = (const float*)d_in[15];
    const float* cb1   = (const float*)d_in[16];
    const float* cw2   = (const float*)d_in[17];
    const float* fc1w  = (const float*)d_in[18];
    const float* fc1b  = (const float*)d_in[19];
    const float* fc2w  = (const float*)d_in[20];
    const float* fc2b  = (const float*)d_in[21];
    // d_in[22], d_in[23] = edge_row/edge_col (recomputed analytically)

    const size_t smem_bytes = (size_t)SMEM_FLOATS * sizeof(float);
    cudaFuncSetAttribute(egnn_critic_kernel,
                         cudaFuncAttributeMaxDynamicSharedMemorySize,
                         (int)smem_bytes);

    int copy_rnn = (out_size >= NB + NB*HID) ? 1 : 0;

    egnn_critic_kernel<<<NB, BLK, smem_bytes>>>(
        obs, rnn, emb_w, emb_b, ew1, eb1, ew2, eb2, attw, attb,
        nw1, nb1, nw2, nb2, cw1, cb1, cw2, fc1w, fc1b, fc2w, fc2b,
        (float*)d_out, copy_rnn);
}

// round 14
// speedup vs baseline: 2.1269x; 1.5466x over previous
#include <cuda_runtime.h>
#include <math.h>

#define NNODE 20
#define NEDGE 380
#define HID   64
#define NL    3
#define ETILE 64
#define NTILE 6      // ceil(380/64)
#define SH    68     // stride for h-like [20][*] arrays (float4-aligned)
#define SMM   68     // buf edge-major stride (float4 aligned)
#define BLK   256
#define NB    1024

__device__ __forceinline__ float tanh_a(float v){
    float r; asm("tanh.approx.f32 %0, %1;" : "=f"(r) : "f"(v)); return r;
}
__device__ __forceinline__ float silu_f(float v){
    return __fdividef(v, 1.f + __expf(-v));
}
__device__ __forceinline__ float sigm_f(float v){
    return __fdividef(1.f, 1.f + __expf(-v));
}
__device__ __forceinline__ float tf32r(float v){
    unsigned int u; asm("cvt.rna.tf32.f32 %0, %1;" : "=r"(u) : "f"(v));
    return __uint_as_float(u);
}

// packed fp32x2 helpers (sm_103a FFMA2 path — node phases)
__device__ __forceinline__ unsigned long long dup2(float v){
    unsigned long long r;
    asm("mov.b64 %0, {%1, %1};" : "=l"(r) : "r"(__float_as_uint(v)));
    return r;
}
__device__ __forceinline__ void ffma2(unsigned long long& acc,
                                      unsigned long long a,
                                      unsigned long long b){
    asm("fma.rn.f32x2 %0, %1, %2, %0;" : "+l"(acc) : "l"(a), "l"(b));
}
__device__ __forceinline__ float2 unpk2(unsigned long long v){
    unsigned int lo, hi;
    asm("mov.b64 {%0, %1}, %2;" : "=r"(lo), "=r"(hi) : "l"(v));
    return make_float2(__uint_as_float(lo), __uint_as_float(hi));
}

// ---- fragment-packed tf32 weight scratch -------------------------------
// index = ((((l*2 + nh)*8 + kt)*4 + nt)*32 + lane)*2 + j
// value = W[l][ k = kt*8 + (lane&3) + j*4 ][ n = nh*32 + nt*8 + (lane>>2) ]
__device__ float W2pk_g[12288];
__device__ float C1pk_g[12288];

__global__ void pack_mma_kernel(const float* __restrict__ ew2,
                                const float* __restrict__ cw1){
    int i = blockIdx.x*blockDim.x + threadIdx.x;
    if (i < 12288){
        int j    = i & 1;
        int lane = (i >> 1) & 31;
        int nt   = (i >> 6) & 3;
        int kt   = (i >> 8) & 7;
        int nh   = (i >> 11) & 1;
        int l    = i >> 12;
        int k = kt*8 + (lane & 3) + j*4;
        int n = nh*32 + nt*8 + (lane >> 2);
        W2pk_g[i] = tf32r(ew2[l*4096 + k*64 + n]);
        C1pk_g[i] = tf32r(cw1[l*4096 + k*64 + n]);
    }
}

#define SMEM_FLOATS (80 + 4*NNODE*SH + ETILE*SMM + 6*64 + 2*ETILE + 384)

// one 64x64x64 GEMM: D(frag regs) = A1(buf, tf32) @ Bpk ; then D -> buf
__device__ __forceinline__ void mma_gemm_64(float* buf, const float* Bpk,
                                            int t){
    int w = t >> 5, lane = t & 31;
    int eb = (w & 3) << 4;          // edge block base
    int nh = (w >> 2) << 5;         // n half base
    int grp = lane >> 2, tig = lane & 3;
    float d[4][4];
    #pragma unroll
    for (int nt = 0; nt < 4; ++nt){
        d[nt][0] = 0.f; d[nt][1] = 0.f; d[nt][2] = 0.f; d[nt][3] = 0.f;
    }
    const float* Ab = buf + (eb + grp)*SMM + tig;
    #pragma unroll
    for (int kt = 0; kt < 8; ++kt){
        unsigned int a0 = __float_as_uint(Ab[kt*8]);
        unsigned int a1 = __float_as_uint(Ab[8*SMM + kt*8]);
        unsigned int a2 = __float_as_uint(Ab[kt*8 + 4]);
        unsigned int a3 = __float_as_uint(Ab[8*SMM + kt*8 + 4]);
        const float2* Bk = reinterpret_cast<const float2*>(Bpk + kt*256) + lane;
        #pragma unroll
        for (int nt = 0; nt < 4; ++nt){
            float2 bv = __ldg(Bk + nt*32);
            unsigned int b0 = __float_as_uint(bv.x);
            unsigned int b1 = __float_as_uint(bv.y);
            asm volatile(
                "mma.sync.aligned.m16n8k8.row.col.f32.tf32.tf32.f32 "
                "{%0,%1,%2,%3}, {%4,%5,%6,%7}, {%8,%9}, {%0,%1,%2,%3};"
                : "+f"(d[nt][0]), "+f"(d[nt][1]), "+f"(d[nt][2]), "+f"(d[nt][3])
                : "r"(a0), "r"(a1), "r"(a2), "r"(a3), "r"(b0), "r"(b1));
        }
    }
    __syncthreads();   // all A reads complete -> overwrite buf with D
    #pragma unroll
    for (int nt = 0; nt < 4; ++nt){
        int col = nh + nt*8 + 2*tig;
        float* p = buf + (eb + grp)*SMM + col;
        *(float2*)p            = make_float2(d[nt][0], d[nt][1]);
        *(float2*)(p + 8*SMM)  = make_float2(d[nt][2], d[nt][3]);
    }
}

__global__ void __launch_bounds__(BLK, 4)
egnn_critic_kernel(
    const float* __restrict__ obs,   const float* __restrict__ rnn,
    const float* __restrict__ emb_w, const float* __restrict__ emb_b,
    const float* __restrict__ ew1,   const float* __restrict__ eb1,
    const float* __restrict__ ew2,   const float* __restrict__ eb2,
    const float* __restrict__ attw,  const float* __restrict__ attb,
    const float* __restrict__ nw1,   const float* __restrict__ nb1,
    const float* __restrict__ nw2,   const float* __restrict__ nb2,
    const float* __restrict__ cw1,   const float* __restrict__ cb1,
    const float* __restrict__ cw2,
    const float* __restrict__ fc1w,  const float* __restrict__ fc1b,
    const float* __restrict__ fc2w,  const float* __restrict__ fc2b,
    float* __restrict__ out, int copy_rnn)
{
    extern __shared__ float sm[];
    float* x0   = sm;
    float* x1   = x0 + NNODE;
    float* aggx = x1 + NNODE;
    float* aggy = aggx + NNODE;
    float* hS   = aggy + NNODE;          // [20][SH]
    float* hA   = hS + NNODE*SH;
    float* hB   = hA + NNODE*SH;
    float* mag  = hB + NNODE*SH;
    float* buf  = mag + NNODE*SH;        // A1 / D / Mm edge-major [64][SMM]
    float* w1c  = buf + ETILE*SMM;
    float* b1v  = w1c + 64;
    float* b2v  = b1v + 64;
    float* avv  = b2v + 64;
    float* cb1v = avv + 64;
    float* c2v  = cb1v + 64;
    float* cdx  = c2v + 64;
    float* cdy  = cdx + ETILE;
    short* rS   = (short*)(cdy + ETILE);      // [380]
    short* cS   = rS + 384;                   // [380]

    const int g = blockIdx.x;
    const int t = threadIdx.x;
    const float* ob = obs + g * NNODE * 10;   // EQU+INV = 10 per node

    // ---- edge index tables (per block, once) ----
    for (int e = t; e < NEDGE; e += BLK){
        int r = e / 19, jj = e - 19*r;
        rS[e] = (short)r;
        cS[e] = (short)(jj + (jj >= r));
    }
    // ---- init x, h ----
    if (t < NNODE){ x0[t] = ob[t*10 + 0]; x1[t] = ob[t*10 + 1]; }
    {
        int d = t & 63, ng = t >> 6;
        #pragma unroll
        for (int q = 0; q < 5; ++q){
            int n = ng + 4*q;
            float acc = emb_b[d];
            #pragma unroll
            for (int k = 0; k < 8; ++k) acc += ob[n*10 + 2 + k] * __ldg(emb_w + k*64 + d);
            hS[n*SH + d] = acc;
        }
    }
    __syncthreads();

    for (int l = 0; l < NL; ++l){
        // ---- stage per-layer vectors, zero accumulators ----
        if (t < 64){
            w1c[t]  = ew1[l*129*64 + 128*64 + t];
            b1v[t]  = eb1[l*64 + t];
            b2v[t]  = eb2[l*64 + t];
            avv[t]  = attw[l*64 + t];
            cb1v[t] = cb1[l*64 + t];
            c2v[t]  = cw2[l*64 + t];
        }
        if (t < NNODE){ aggx[t] = 0.f; aggy[t] = 0.f; }
        for (int i = t; i < NNODE*SH; i += BLK) mag[i] = 0.f;
        __syncthreads();

        const float ab = __ldg(attb + l);

        // ---- hA = h @ W1[0:64] + b1 (folded), hB = h @ W1[64:128] (FFMA2) ----
        {
            int half = t >> 7;
            int tx = t & 15;
            int ty = (t >> 4) & 7;
            if (ty < 5){
                int n0 = ty, n1 = ty + 5, n2 = ty + 10, n3 = ty + 15;
                unsigned long long acc[4][2];
                #pragma unroll
                for (int i = 0; i < 4; ++i){ acc[i][0] = 0ull; acc[i][1] = 0ull; }
                const ulonglong2* Wg =
                    reinterpret_cast<const ulonglong2*>(ew1 + l*129*64 + half*4096) + tx;
                #pragma unroll 4
                for (int k4 = 0; k4 < 64; k4 += 4){
                    float4 a0 = *(const float4*)(hS + n0*SH + k4);
                    float4 a1 = *(const float4*)(hS + n1*SH + k4);
                    float4 a2 = *(const float4*)(hS + n2*SH + k4);
                    float4 a3 = *(const float4*)(hS + n3*SH + k4);
                    #pragma unroll
                    for (int kk = 0; kk < 4; ++kk){
                        ulonglong2 b = __ldg(Wg + (k4 + kk)*16);
                        unsigned long long d0 = dup2(((float*)&a0)[kk]);
                        unsigned long long d1 = dup2(((float*)&a1)[kk]);
                        unsigned long long d2 = dup2(((float*)&a2)[kk]);
                        unsigned long long d3 = dup2(((float*)&a3)[kk]);
                        ffma2(acc[0][0], d0, b.x); ffma2(acc[0][1], d0, b.y);
                        ffma2(acc[1][0], d1, b.x); ffma2(acc[1][1], d1, b.y);
                        ffma2(acc[2][0], d2, b.x); ffma2(acc[2][1], d2, b.y);
                        ffma2(acc[3][0], d3, b.x); ffma2(acc[3][1], d3, b.y);
                    }
                }
                float* dst = half ? hB : hA;
                float4 bf = half ? make_float4(0.f,0.f,0.f,0.f)
                                 : *(const float4*)(b1v + 4*tx);
                int nn[4] = {n0, n1, n2, n3};
                #pragma unroll
                for (int i = 0; i < 4; ++i){
                    float2 p0 = unpk2(acc[i][0]);
                    float2 p1 = unpk2(acc[i][1]);
                    *(float4*)(dst + nn[i]*SH + 4*tx) =
                        make_float4(p0.x + bf.x, p0.y + bf.y, p1.x + bf.z, p1.y + bf.w);
                }
            }
        }
        __syncthreads();

        const float* W2pk = W2pk_g + (l*2)*2048;   // [nh][kt][nt][lane][2] : nh stride 2048
        const float* C1pk = C1pk_g + (l*2)*2048;

        // ---- edge tiles (64 edges) ----
        for (int tile = 0; tile < NTILE; ++tile){
            const int e0 = tile * ETILE;

            // A1 = tf32(silu(hA[r] + hB[c] + radial*w1c))   (b1 already in hA)
            {
                int le = t & 63, kg = t >> 6;   // kg: 16 ks each
                int e = e0 + le;
                bool v = (e < NEDGE);
                int r = 0, c = 0; float radial = 0.f;
                if (v){
                    r = rS[e]; c = cS[e];
                    float dx = x0[r] - x0[c], dy = x1[r] - x1[c];
                    radial = dx*dx + dy*dy;
                    if (kg == 0){
                        float inv = 1.f / (sqrtf(radial) + 1e-8f);
                        cdx[le] = dx * inv; cdy[le] = dy * inv;
                    }
                }
                int kbeg = kg * 16;
                #pragma unroll 4
                for (int k4 = kbeg; k4 < kbeg + 16; k4 += 4){
                    float4 o4 = make_float4(0.f, 0.f, 0.f, 0.f);
                    if (v){
                        float4 ha = *(const float4*)(hA + r*SH + k4);
                        float4 hb = *(const float4*)(hB + c*SH + k4);
                        float4 wc = *(const float4*)(w1c + k4);
                        o4.x = tf32r(silu_f(fmaf(radial, wc.x, ha.x + hb.x)));
                        o4.y = tf32r(silu_f(fmaf(radial, wc.y, ha.y + hb.y)));
                        o4.z = tf32r(silu_f(fmaf(radial, wc.z, ha.z + hb.z)));
                        o4.w = tf32r(silu_f(fmaf(radial, wc.w, ha.w + hb.w)));
                    }
                    *(float4*)(buf + le*SMM + k4) = o4;
                }
            }
            __syncthreads();

            // GEMM1 core on tensor pipe: D = A1 @ W2  (D lands in buf)
            {
                int w = t >> 5;
                mma_gemm_64(buf, W2pk + ((w >> 2) ? 2048 : 0), t);
            }
            __syncthreads();

            // epilogue 1: m = silu(D + b2) * sigmoid(att); Mm (tf32) in-place;
            // fused m_agg segment sum
            {
                int tx = t & 15, ty = t >> 4;
                float mz[4][4];
                float attp[4];
                #pragma unroll
                for (int i = 0; i < 4; ++i){
                    float4 dv = *(const float4*)(buf + (4*ty+i)*SMM + 4*tx);
                    float z0 = silu_f(dv.x + b2v[4*tx + 0]);
                    float z1 = silu_f(dv.y + b2v[4*tx + 1]);
                    float z2 = silu_f(dv.z + b2v[4*tx + 2]);
                    float z3 = silu_f(dv.w + b2v[4*tx + 3]);
                    mz[i][0] = z0; mz[i][1] = z1; mz[i][2] = z2; mz[i][3] = z3;
                    attp[i] = z0*avv[4*tx+0] + z1*avv[4*tx+1]
                            + z2*avv[4*tx+2] + z3*avv[4*tx+3];
                }
                #pragma unroll
                for (int m = 8; m >= 1; m >>= 1){
                    #pragma unroll
                    for (int i = 0; i < 4; ++i)
                        attp[i] += __shfl_xor_sync(0xffffffffu, attp[i], m, 16);
                }
                float sg[4];
                #pragma unroll
                for (int i = 0; i < 4; ++i) sg[i] = sigm_f(attp[i] + ab);

                float s0 = 0.f, s1 = 0.f, s2 = 0.f, s3 = 0.f;
                int curr = -1;
                #pragma unroll
                for (int i = 0; i < 4; ++i){
                    float m0 = mz[i][0]*sg[i], m1 = mz[i][1]*sg[i];
                    float m2 = mz[i][2]*sg[i], m3 = mz[i][3]*sg[i];
                    // in-place store (same addresses this thread read) as tf32
                    *(float4*)(buf + (4*ty + i)*SMM + 4*tx) =
                        make_float4(tf32r(m0), tf32r(m1), tf32r(m2), tf32r(m3));
                    int e = e0 + 4*ty + i;
                    if (e < NEDGE){
                        int r = rS[e];
                        if (r != curr){
                            if (curr >= 0){
                                atomicAdd(mag + curr*SH + 4*tx + 0, s0);
                                atomicAdd(mag + curr*SH + 4*tx + 1, s1);
                                atomicAdd(mag + curr*SH + 4*tx + 2, s2);
                                atomicAdd(mag + curr*SH + 4*tx + 3, s3);
                            }
                            curr = r; s0 = s1 = s2 = s3 = 0.f;
                        }
                        s0 += m0; s1 += m1; s2 += m2; s3 += m3;
                    }
                }
                if (curr >= 0){
                    atomicAdd(mag + curr*SH + 4*tx + 0, s0);
                    atomicAdd(mag + curr*SH + 4*tx + 1, s1);
                    atomicAdd(mag + curr*SH + 4*tx + 2, s2);
                    atomicAdd(mag + curr*SH + 4*tx + 3, s3);
                }
            }
            __syncthreads();

            // GEMM2 core on tensor pipe: D = Mm @ C1  (D lands in buf)
            {
                int w = t >> 5;
                mma_gemm_64(buf, C1pk + ((w >> 2) ? 2048 : 0), t);
            }
            __syncthreads();

            // epilogue 2: t3 = silu(D + cb1); w = tanh(t3 . c2v); scatter coords
            {
                int tx = t & 15, ty = t >> 4;
                float wp[4];
                #pragma unroll
                for (int i = 0; i < 4; ++i){
                    float4 dv = *(const float4*)(buf + (4*ty+i)*SMM + 4*tx);
                    float z0 = silu_f(dv.x + cb1v[4*tx + 0]);
                    float z1 = silu_f(dv.y + cb1v[4*tx + 1]);
                    float z2 = silu_f(dv.z + cb1v[4*tx + 2]);
                    float z3 = silu_f(dv.w + cb1v[4*tx + 3]);
                    wp[i] = z0*c2v[4*tx+0] + z1*c2v[4*tx+1]
                          + z2*c2v[4*tx+2] + z3*c2v[4*tx+3];
                }
                #pragma unroll
                for (int m = 8; m >= 1; m >>= 1){
                    #pragma unroll
                    for (int i = 0; i < 4; ++i)
                        wp[i] += __shfl_xor_sync(0xffffffffu, wp[i], m, 16);
                }
                if (tx == 0){
                    #pragma unroll
                    for (int i = 0; i < 4; ++i){
                        int le = 4*ty + i, e = e0 + le;
                        if (e < NEDGE){
                            float w = tanh_a(wp[i]);
                            int r = rS[e];
                            atomicAdd(aggx + r, cdx[le] * w);
                            atomicAdd(aggy + r, cdy[le] * w);
                        }
                    }
                }
            }
            __syncthreads();   // protects buf/cdx/cdy before next tile
        } // tiles

        // ---- x update (cnt == 19 exactly) ----
        if (t < NNODE){
            x0[t] += aggx[t] * (1.f/19.f);
            x1[t] += aggy[t] * (1.f/19.f);
        }

        // ---- node MLP pass1 (FFMA2): z1 = silu([h,m_agg]@nw1 + nb1) ----
        float* z1 = buf;
        {
            int tx = t & 15, ty = t >> 4;
            if (ty < 10){
                int n0 = ty, n1 = ty + 10;
                unsigned long long acc[2][2];
                acc[0][0]=0ull; acc[0][1]=0ull; acc[1][0]=0ull; acc[1][1]=0ull;
                const ulonglong2* Wg =
                    reinterpret_cast<const ulonglong2*>(nw1 + l*8192) + tx;
                #pragma unroll 4
                for (int k4 = 0; k4 < 64; k4 += 4){
                    float4 a0 = *(const float4*)(hS + n0*SH + k4);
                    float4 a1 = *(const float4*)(hS + n1*SH + k4);
                    #pragma unroll
                    for (int kk = 0; kk < 4; ++kk){
                        ulonglong2 b = __ldg(Wg + (k4 + kk)*16);
                        unsigned long long d0 = dup2(((float*)&a0)[kk]);
                        unsigned long long d1 = dup2(((float*)&a1)[kk]);
                        ffma2(acc[0][0], d0, b.x); ffma2(acc[0][1], d0, b.y);
                        ffma2(acc[1][0], d1, b.x); ffma2(acc[1][1], d1, b.y);
                    }
                }
                #pragma unroll 4
                for (int k4 = 0; k4 < 64; k4 += 4){
                    float4 a0 = *(const float4*)(mag + n0*SH + k4);
                    float4 a1 = *(const float4*)(mag + n1*SH + k4);
                    #pragma unroll
                    for (int kk = 0; kk < 4; ++kk){
                        ulonglong2 b = __ldg(Wg + (64 + k4 + kk)*16);
                        unsigned long long d0 = dup2(((float*)&a0)[kk]);
                        unsigned long long d1 = dup2(((float*)&a1)[kk]);
                        ffma2(acc[0][0], d0, b.x); ffma2(acc[0][1], d0, b.y);
                        ffma2(acc[1][0], d1, b.x); ffma2(acc[1][1], d1, b.y);
                    }
                }
                float4 bb = __ldg(reinterpret_cast<const float4*>(nb1 + l*64) + tx);
                {
                    float2 p0 = unpk2(acc[0][0]), p1 = unpk2(acc[0][1]);
                    *(float4*)(z1 + n0*SH + 4*tx) = make_float4(
                        silu_f(p0.x + bb.x), silu_f(p0.y + bb.y),
                        silu_f(p1.x + bb.z), silu_f(p1.y + bb.w));
                }
                {
                    float2 p0 = unpk2(acc[1][0]), p1 = unpk2(acc[1][1]);
                    *(float4*)(z1 + n1*SH + 4*tx) = make_float4(
                        silu_f(p0.x + bb.x), silu_f(p0.y + bb.y),
                        silu_f(p1.x + bb.z), silu_f(p1.y + bb.w));
                }
            }
        }
        __syncthreads();

        // ---- node MLP pass2 (FFMA2): h += z1 @ nw2 + nb2 ----
        {
            int tx = t & 15, ty = t >> 4;
            if (ty < 10){
                int n0 = ty, n1 = ty + 10;
                unsigned long long acc[2][2];
                acc[0][0]=0ull; acc[0][1]=0ull; acc[1][0]=0ull; acc[1][1]=0ull;
                const ulonglong2* Wg =
                    reinterpret_cast<const ulonglong2*>(nw2 + l*4096) + tx;
                #pragma unroll 4
                for (int k4 = 0; k4 < 64; k4 += 4){
                    float4 a0 = *(const float4*)(z1 + n0*SH + k4);
                    float4 a1 = *(const float4*)(z1 + n1*SH + k4);
                    #pragma unroll
                    for (int kk = 0; kk < 4; ++kk){
                        ulonglong2 b = __ldg(Wg + (k4 + kk)*16);
                        unsigned long long d0 = dup2(((float*)&a0)[kk]);
                        unsigned long long d1 = dup2(((float*)&a1)[kk]);
                        ffma2(acc[0][0], d0, b.x); ffma2(acc[0][1], d0, b.y);
                        ffma2(acc[1][0], d1, b.x); ffma2(acc[1][1], d1, b.y);
                    }
                }
                float4 bb = __ldg(reinterpret_cast<const float4*>(nb2 + l*64) + tx);
                {
                    float2 p0 = unpk2(acc[0][0]), p1 = unpk2(acc[0][1]);
                    float4 h0 = *(const float4*)(hS + n0*SH + 4*tx);
                    h0.x += p0.x + bb.x; h0.y += p0.y + bb.y;
                    h0.z += p1.x + bb.z; h0.w += p1.y + bb.w;
                    *(float4*)(hS + n0*SH + 4*tx) = h0;
                }
                {
                    float2 p0 = unpk2(acc[1][0]), p1 = unpk2(acc[1][1]);
                    float4 h1 = *(const float4*)(hS + n1*SH + 4*tx);
                    h1.x += p0.x + bb.x; h1.y += p0.y + bb.y;
                    h1.z += p1.x + bb.z; h1.w += p1.y + bb.w;
                    *(float4*)(hS + n1*SH + 4*tx) = h1;
                }
            }
        }
        __syncthreads();
    } // layers

    // ---- value head (FFMA2): z1 = tanh([xsq,h] @ fc1w + fc1b) ----
    float* z1 = buf;
    {
        int tx = t & 15, ty = t >> 4;
        if (ty < 10){
            int n0 = ty, n1 = ty + 10;
            unsigned long long acc[2][2];
            acc[0][0]=0ull; acc[0][1]=0ull; acc[1][0]=0ull; acc[1][1]=0ull;
            const ulonglong2* Wg =
                reinterpret_cast<const ulonglong2*>(fc1w + 64) + tx;   // rows 1..64
            #pragma unroll 4
            for (int k4 = 0; k4 < 64; k4 += 4){
                float4 a0 = *(const float4*)(hS + n0*SH + k4);
                float4 a1 = *(const float4*)(hS + n1*SH + k4);
                #pragma unroll
                for (int kk = 0; kk < 4; ++kk){
                    ulonglong2 b = __ldg(Wg + (k4 + kk)*16);
                    unsigned long long d0 = dup2(((float*)&a0)[kk]);
                    unsigned long long d1 = dup2(((float*)&a1)[kk]);
                    ffma2(acc[0][0], d0, b.x); ffma2(acc[0][1], d0, b.y);
                    ffma2(acc[1][0], d1, b.x); ffma2(acc[1][1], d1, b.y);
                }
            }
            float4 w0 = __ldg(reinterpret_cast<const float4*>(fc1w) + tx);  // xsq row
            float4 bb = __ldg(reinterpret_cast<const float4*>(fc1b) + tx);
            float xsq0 = x0[n0]*x0[n0] + x1[n0]*x1[n0];
            float xsq1 = x0[n1]*x0[n1] + x1[n1]*x1[n1];
            {
                float2 p0 = unpk2(acc[0][0]), p1 = unpk2(acc[0][1]);
                *(float4*)(z1 + n0*SH + 4*tx) = make_float4(
                    tanh_a(fmaf(xsq0, w0.x, p0.x + bb.x)),
                    tanh_a(fmaf(xsq0, w0.y, p0.y + bb.y)),
                    tanh_a(fmaf(xsq0, w0.z, p1.x + bb.z)),
                    tanh_a(fmaf(xsq0, w0.w, p1.y + bb.w)));
            }
            {
                float2 p0 = unpk2(acc[1][0]), p1 = unpk2(acc[1][1]);
                *(float4*)(z1 + n1*SH + 4*tx) = make_float4(
                    tanh_a(fmaf(xsq1, w0.x, p0.x + bb.x)),
                    tanh_a(fmaf(xsq1, w0.y, p0.y + bb.y)),
                    tanh_a(fmaf(xsq1, w0.z, p1.x + bb.z)),
                    tanh_a(fmaf(xsq1, w0.w, p1.y + bb.w)));
            }
        }
    }
    __syncthreads();
    if (t < 32){
        float v = 0.f;
        if (t < NNODE){
            v = __ldg(fc2b);
            #pragma unroll 4
            for (int k4 = 0; k4 < 64; k4 += 4){
                float4 z = *(const float4*)(z1 + t*SH + k4);
                float4 w = *(const float4*)(fc2w + k4);
                v = fmaf(z.x, w.x, v); v = fmaf(z.y, w.y, v);
                v = fmaf(z.z, w.z, v); v = fmaf(z.w, w.w, v);
            }
        }
        #pragma unroll
        for (int m = 16; m >= 1; m >>= 1) v += __shfl_xor_sync(0xffffffffu, v, m);
        if (t == 0) out[g] = v * (1.f / NNODE);
    }
    // rnn_states passthrough
    if (copy_rnn && t < 64) out[NB + g*64 + t] = rnn[g*64 + t];
}

extern "C" void kernel_launch(void* const* d_in, const int* in_sizes, int n_in,
                              void* d_out, int out_size)
{
    const float* obs   = (const float*)d_in[0];
    const float* rnn   = (const float*)d_in[1];
    // d_in[2] = masks (unused)
    const float* emb_w = (const float*)d_in[3];
    const float* emb_b = (const float*)d_in[4];
    const float* ew1   = (const float*)d_in[5];
    const float* eb1   = (const float*)d_in[6];
    const float* ew2   = (const float*)d_in[7];
    const float* eb2   = (const float*)d_in[8];
    const float* attw  = (const float*)d_in[9];
    const float* attb  = (const float*)d_in[10];
    const float* nw1   = (const float*)d_in[11];
    const float* nb1   = (const float*)d_in[12];
    const float* nw2   = (const float*)d_in[13];
    const float* nb2   = (const float*)d_in[14];
    const float* cw1   = (const float*)d_in[15];
    const float* cb1   = (const float*)d_in[16];
    const float* cw2   = (const float*)d_in[17];
    const float* fc1w  = (const float*)d_in[18];
    const float* fc1b  = (const float*)d_in[19];
    const float* fc2w  = (const float*)d_in[20];
    const float* fc2b  = (const float*)d_in[21];
    // d_in[22], d_in[23] = edge_row/edge_col (recomputed analytically)

    // pack fragment-ordered tf32 weights (graph-capturable kernel launch)
    pack_mma_kernel<<<48, 256>>>(ew2, cw1);

    const size_t smem_bytes = (size_t)SMEM_FLOATS * sizeof(float);
    cudaFuncSetAttribute(egnn_critic_kernel,
                         cudaFuncAttributeMaxDynamicSharedMemorySize,
                         (int)smem_bytes);

    int copy_rnn = (out_size >= NB + NB*HID) ? 1 : 0;

    egnn_critic_kernel<<<NB, BLK, smem_bytes>>>(
        obs, rnn, emb_w, emb_b, ew1, eb1, ew2, eb2, attw, attb,
        nw1, nb1, nw2, nb2, cw1, cb1, cw2, fc1w, fc1b, fc2w, fc2b,
        (float*)d_out, copy_rnn);
}

// round 15
// speedup vs baseline: 2.4331x; 1.1440x over previous
#include <cuda_runtime.h>
#include <math.h>

#define NNODE 20
#define NEDGE 380
#define HID   64
#define NL    3
#define ETILE 64
#define NTILE 6      // ceil(380/64)
#define SH    68     // stride for h-like [20][*] arrays (float4-aligned)
#define SMM   68     // buf edge-major stride (float4 aligned)
#define BLK   256
#define NB    1024

__device__ __forceinline__ float tanh_a(float v){
    float r; asm("tanh.approx.f32 %0, %1;" : "=f"(r) : "f"(v)); return r;
}
__device__ __forceinline__ float silu_f(float v){
    return __fdividef(v, 1.f + __expf(-v));
}
__device__ __forceinline__ float sigm_f(float v){
    return __fdividef(1.f, 1.f + __expf(-v));
}
__device__ __forceinline__ float tf32r(float v){
    unsigned int u; asm("cvt.rna.tf32.f32 %0, %1;" : "=r"(u) : "f"(v));
    return __uint_as_float(u);
}
__device__ __forceinline__ void mma_tf32(float d[4],
                                         unsigned int a0, unsigned int a1,
                                         unsigned int a2, unsigned int a3,
                                         unsigned int b0, unsigned int b1){
    asm volatile(
        "mma.sync.aligned.m16n8k8.row.col.f32.tf32.tf32.f32 "
        "{%0,%1,%2,%3}, {%4,%5,%6,%7}, {%8,%9}, {%0,%1,%2,%3};"
        : "+f"(d[0]), "+f"(d[1]), "+f"(d[2]), "+f"(d[3])
        : "r"(a0), "r"(a1), "r"(a2), "r"(a3), "r"(b0), "r"(b1));
}

// ---- fragment-packed tf32 weight scratch -------------------------------
// edge layout: index = ((((l*2 + nh)*8 + kt)*4 + nt)*32 + lane)*2 + j
__device__ float W2pk_g[12288];
__device__ float C1pk_g[12288];
// node layout (generic): idx = ((kt*(N/8) + nt)*32 + lane)*2 + j
//   k = kt*8 + (lane&3) + j*4 ;  n = nt*8 + (lane>>2)
__device__ float EW1pk_g[24576];   // per l: K=64, N=128 ([hA|hB] fused), 8192
__device__ float NW1pk_g[24576];   // per l: K=128, N=64, 8192
__device__ float NW2pk_g[12288];   // per l: K=64, N=64, 4096
__device__ float FC1pk_g[4096];    // K=64, N=64 (fc1w rows 1..64)

__global__ void pack_mma_kernel(const float* __restrict__ ew2,
                                const float* __restrict__ cw1){
    int i = blockIdx.x*blockDim.x + threadIdx.x;
    if (i < 12288){
        int j    = i & 1;
        int lane = (i >> 1) & 31;
        int nt   = (i >> 6) & 3;
        int kt   = (i >> 8) & 7;
        int nh   = (i >> 11) & 1;
        int l    = i >> 12;
        int k = kt*8 + (lane & 3) + j*4;
        int n = nh*32 + nt*8 + (lane >> 2);
        W2pk_g[i] = tf32r(ew2[l*4096 + k*64 + n]);
        C1pk_g[i] = tf32r(cw1[l*4096 + k*64 + n]);
    }
}

__global__ void pack_node_kernel(const float* __restrict__ ew1,
                                 const float* __restrict__ nw1,
                                 const float* __restrict__ nw2,
                                 const float* __restrict__ fc1w){
    int i = blockIdx.x*blockDim.x + threadIdx.x;
    if (i < 24576){
        // EW1pk: K=64, N=128 ; n<64 -> W1[k][n] (hA), n>=64 -> W1[64+k][n-64] (hB)
        int l = i / 8192, r = i % 8192;
        int j = r & 1, lane = (r >> 1) & 31, nt = (r >> 6) & 15, kt = r >> 10;
        int k = kt*8 + (lane & 3) + j*4;
        int n = nt*8 + (lane >> 2);
        const float* src = ew1 + l*8256;   // 129*64
        float v = (n < 64) ? src[k*64 + n] : src[(64 + k)*64 + (n - 64)];
        EW1pk_g[i] = tf32r(v);
    } else if (i < 49152){
        // NW1pk: K=128, N=64
        int r0 = i - 24576;
        int l = r0 / 8192, r = r0 % 8192;
        int j = r & 1, lane = (r >> 1) & 31, nt = (r >> 6) & 7, kt = r >> 9;
        int k = kt*8 + (lane & 3) + j*4;
        int n = nt*8 + (lane >> 2);
        NW1pk_g[r0] = tf32r(nw1[l*8192 + k*64 + n]);
    } else if (i < 61440){
        // NW2pk: K=64, N=64
        int r0 = i - 49152;
        int l = r0 / 4096, r = r0 % 4096;
        int j = r & 1, lane = (r >> 1) & 31, nt = (r >> 6) & 7, kt = r >> 9;
        int k = kt*8 + (lane & 3) + j*4;
        int n = nt*8 + (lane >> 2);
        NW2pk_g[r0] = tf32r(nw2[l*4096 + k*64 + n]);
    } else if (i < 65536){
        // FC1pk: K=64, N=64 (rows 1..64 of fc1w)
        int r = i - 61440;
        int j = r & 1, lane = (r >> 1) & 31, nt = (r >> 6) & 7, kt = r >> 9;
        int k = kt*8 + (lane & 3) + j*4;
        int n = nt*8 + (lane >> 2);
        FC1pk_g[r] = tf32r(fc1w[(1 + k)*64 + n]);
    }
}

#define SMEM_FLOATS (80 + 4*NNODE*SH + ETILE*SMM + 6*64 + 2*ETILE + 384)

// one 64x64x64 GEMM: D(frag regs) = A1(buf, tf32) @ Bpk ; then D -> buf
__device__ __forceinline__ void mma_gemm_64(float* buf, const float* Bpk,
                                            int t){
    int w = t >> 5, lane = t & 31;
    int eb = (w & 3) << 4;          // edge block base
    int nh = (w >> 2) << 5;         // n half base
    int grp = lane >> 2, tig = lane & 3;
    float d[4][4];
    #pragma unroll
    for (int nt = 0; nt < 4; ++nt){
        d[nt][0] = 0.f; d[nt][1] = 0.f; d[nt][2] = 0.f; d[nt][3] = 0.f;
    }
    const float* Ab = buf + (eb + grp)*SMM + tig;
    #pragma unroll
    for (int kt = 0; kt < 8; ++kt){
        unsigned int a0 = __float_as_uint(Ab[kt*8]);
        unsigned int a1 = __float_as_uint(Ab[8*SMM + kt*8]);
        unsigned int a2 = __float_as_uint(Ab[kt*8 + 4]);
        unsigned int a3 = __float_as_uint(Ab[8*SMM + kt*8 + 4]);
        const float2* Bk = reinterpret_cast<const float2*>(Bpk + kt*256) + lane;
        #pragma unroll
        for (int nt = 0; nt < 4; ++nt){
            float2 bv = __ldg(Bk + nt*32);
            mma_tf32(d[nt], a0, a1, a2, a3,
                     __float_as_uint(bv.x), __float_as_uint(bv.y));
        }
    }
    __syncthreads();   // all A reads complete -> overwrite buf with D
    #pragma unroll
    for (int nt = 0; nt < 4; ++nt){
        int col = nh + nt*8 + 2*tig;
        float* p = buf + (eb + grp)*SMM + col;
        *(float2*)p            = make_float2(d[nt][0], d[nt][1]);
        *(float2*)(p + 8*SMM)  = make_float2(d[nt][2], d[nt][3]);
    }
}

__global__ void __launch_bounds__(BLK, 4)
egnn_critic_kernel(
    const float* __restrict__ obs,   const float* __restrict__ rnn,
    const float* __restrict__ emb_w, const float* __restrict__ emb_b,
    const float* __restrict__ ew1,   const float* __restrict__ eb1,
    const float* __restrict__ ew2,   const float* __restrict__ eb2,
    const float* __restrict__ attw,  const float* __restrict__ attb,
    const float* __restrict__ nw1,   const float* __restrict__ nb1,
    const float* __restrict__ nw2,   const float* __restrict__ nb2,
    const float* __restrict__ cw1,   const float* __restrict__ cb1,
    const float* __restrict__ cw2,
    const float* __restrict__ fc1w,  const float* __restrict__ fc1b,
    const float* __restrict__ fc2w,  const float* __restrict__ fc2b,
    float* __restrict__ out, int copy_rnn)
{
    extern __shared__ float sm[];
    float* x0   = sm;
    float* x1   = x0 + NNODE;
    float* aggx = x1 + NNODE;
    float* aggy = aggx + NNODE;
    float* hS   = aggy + NNODE;          // [20][SH]
    float* hA   = hS + NNODE*SH;
    float* hB   = hA + NNODE*SH;
    float* mag  = hB + NNODE*SH;
    float* buf  = mag + NNODE*SH;        // A1 / D / Mm edge-major [64][SMM]
    float* w1c  = buf + ETILE*SMM;
    float* b1v  = w1c + 64;
    float* b2v  = b1v + 64;
    float* avv  = b2v + 64;
    float* cb1v = avv + 64;
    float* c2v  = cb1v + 64;
    float* cdx  = c2v + 64;
    float* cdy  = cdx + ETILE;
    short* rS   = (short*)(cdy + ETILE);      // [380]
    short* cS   = rS + 384;                   // [380]

    const int g = blockIdx.x;
    const int t = threadIdx.x;
    const int w = t >> 5, lane = t & 31;
    const int mt = w & 1, nc = w >> 1;        // node-GEMM warp mapping
    const int grp = lane >> 2, tig = lane & 3;
    const int r0 = 16*mt + grp;               // node rows r0, r0+8
    const float* ob = obs + g * NNODE * 10;   // EQU+INV = 10 per node

    // ---- edge index tables (per block, once) ----
    for (int e = t; e < NEDGE; e += BLK){
        int r = e / 19, jj = e - 19*r;
        rS[e] = (short)r;
        cS[e] = (short)(jj + (jj >= r));
    }
    // ---- init x, h ----
    if (t < NNODE){ x0[t] = ob[t*10 + 0]; x1[t] = ob[t*10 + 1]; }
    {
        int d = t & 63, ng = t >> 6;
        #pragma unroll
        for (int q = 0; q < 5; ++q){
            int n = ng + 4*q;
            float acc = emb_b[d];
            #pragma unroll
            for (int k = 0; k < 8; ++k) acc += ob[n*10 + 2 + k] * __ldg(emb_w + k*64 + d);
            hS[n*SH + d] = acc;
        }
    }
    __syncthreads();

    for (int l = 0; l < NL; ++l){
        // ---- stage per-layer vectors, zero accumulators ----
        if (t < 64){
            w1c[t]  = ew1[l*129*64 + 128*64 + t];
            b1v[t]  = eb1[l*64 + t];
            b2v[t]  = eb2[l*64 + t];
            avv[t]  = attw[l*64 + t];
            cb1v[t] = cb1[l*64 + t];
            c2v[t]  = cw2[l*64 + t];
        }
        if (t < NNODE){ aggx[t] = 0.f; aggy[t] = 0.f; }
        for (int i = t; i < NNODE*SH; i += BLK) mag[i] = 0.f;
        __syncthreads();

        const float ab = __ldg(attb + l);

        // ---- hA|hB = h @ [W1a|W1b] via MMA  (N=128; bias b1 folded into hA) ----
        {
            float d[4][4];
            #pragma unroll
            for (int q = 0; q < 4; ++q){ d[q][0]=0.f; d[q][1]=0.f; d[q][2]=0.f; d[q][3]=0.f; }
            const float* Ab = hS + r0*SH + tig;
            const float* Bpk = EW1pk_g + l*8192;
            #pragma unroll
            for (int kt = 0; kt < 8; ++kt){
                unsigned int a0 = __float_as_uint(Ab[kt*8]);
                unsigned int a1 = __float_as_uint(Ab[8*SH + kt*8]);
                unsigned int a2 = __float_as_uint(Ab[kt*8 + 4]);
                unsigned int a3 = __float_as_uint(Ab[8*SH + kt*8 + 4]);
                #pragma unroll
                for (int q = 0; q < 4; ++q){
                    int nt = nc*4 + q;
                    float2 bv = __ldg(reinterpret_cast<const float2*>(Bpk) + (kt*16 + nt)*32 + lane);
                    mma_tf32(d[q], a0, a1, a2, a3,
                             __float_as_uint(bv.x), __float_as_uint(bv.y));
                }
            }
            __syncthreads();   // hS reads done before hA/hB writes (alias safety)
            #pragma unroll
            for (int q = 0; q < 4; ++q){
                int n = nc*32 + q*8 + 2*tig;
                bool isA = (n < 64);
                float* dst = isA ? hA : hB;
                int col = isA ? n : n - 64;
                float bb0 = isA ? b1v[col]     : 0.f;
                float bb1 = isA ? b1v[col + 1] : 0.f;
                if (r0 < NNODE){
                    dst[r0*SH + col]     = d[q][0] + bb0;
                    dst[r0*SH + col + 1] = d[q][1] + bb1;
                }
                if (r0 + 8 < NNODE){
                    dst[(r0+8)*SH + col]     = d[q][2] + bb0;
                    dst[(r0+8)*SH + col + 1] = d[q][3] + bb1;
                }
            }
        }
        __syncthreads();

        const float* W2pk = W2pk_g + (l*2)*2048;
        const float* C1pk = C1pk_g + (l*2)*2048;

        // ---- edge tiles (64 edges) ----
        for (int tile = 0; tile < NTILE; ++tile){
            const int e0 = tile * ETILE;

            // A1 = tf32(silu(hA[r] + hB[c] + radial*w1c))   (b1 already in hA)
            {
                int le = t & 63, kg = t >> 6;
                int e = e0 + le;
                bool v = (e < NEDGE);
                int r = 0, c = 0; float radial = 0.f;
                if (v){
                    r = rS[e]; c = cS[e];
                    float dx = x0[r] - x0[c], dy = x1[r] - x1[c];
                    radial = dx*dx + dy*dy;
                    if (kg == 0){
                        float inv = 1.f / (sqrtf(radial) + 1e-8f);
                        cdx[le] = dx * inv; cdy[le] = dy * inv;
                    }
                }
                int kbeg = kg * 16;
                #pragma unroll 4
                for (int k4 = kbeg; k4 < kbeg + 16; k4 += 4){
                    float4 o4 = make_float4(0.f, 0.f, 0.f, 0.f);
                    if (v){
                        float4 ha = *(const float4*)(hA + r*SH + k4);
                        float4 hb = *(const float4*)(hB + c*SH + k4);
                        float4 wc = *(const float4*)(w1c + k4);
                        o4.x = tf32r(silu_f(fmaf(radial, wc.x, ha.x + hb.x)));
                        o4.y = tf32r(silu_f(fmaf(radial, wc.y, ha.y + hb.y)));
                        o4.z = tf32r(silu_f(fmaf(radial, wc.z, ha.z + hb.z)));
                        o4.w = tf32r(silu_f(fmaf(radial, wc.w, ha.w + hb.w)));
                    }
                    *(float4*)(buf + le*SMM + k4) = o4;
                }
            }
            __syncthreads();

            // GEMM1 core on tensor pipe: D = A1 @ W2
            mma_gemm_64(buf, W2pk + ((w >> 2) ? 2048 : 0), t);
            __syncthreads();

            // epilogue 1: m = silu(D + b2) * sigmoid(att); Mm (tf32) in-place;
            // fused m_agg segment sum
            {
                int tx = t & 15, ty = t >> 4;
                float mz[4][4];
                float attp[4];
                #pragma unroll
                for (int i = 0; i < 4; ++i){
                    float4 dv = *(const float4*)(buf + (4*ty+i)*SMM + 4*tx);
                    float z0 = silu_f(dv.x + b2v[4*tx + 0]);
                    float z1 = silu_f(dv.y + b2v[4*tx + 1]);
                    float z2 = silu_f(dv.z + b2v[4*tx + 2]);
                    float z3 = silu_f(dv.w + b2v[4*tx + 3]);
                    mz[i][0] = z0; mz[i][1] = z1; mz[i][2] = z2; mz[i][3] = z3;
                    attp[i] = z0*avv[4*tx+0] + z1*avv[4*tx+1]
                            + z2*avv[4*tx+2] + z3*avv[4*tx+3];
                }
                #pragma unroll
                for (int m = 8; m >= 1; m >>= 1){
                    #pragma unroll
                    for (int i = 0; i < 4; ++i)
                        attp[i] += __shfl_xor_sync(0xffffffffu, attp[i], m, 16);
                }
                float sg[4];
                #pragma unroll
                for (int i = 0; i < 4; ++i) sg[i] = sigm_f(attp[i] + ab);

                float s0 = 0.f, s1 = 0.f, s2 = 0.f, s3 = 0.f;
                int curr = -1;
                #pragma unroll
                for (int i = 0; i < 4; ++i){
                    float m0 = mz[i][0]*sg[i], m1 = mz[i][1]*sg[i];
                    float m2 = mz[i][2]*sg[i], m3 = mz[i][3]*sg[i];
                    *(float4*)(buf + (4*ty + i)*SMM + 4*tx) =
                        make_float4(tf32r(m0), tf32r(m1), tf32r(m2), tf32r(m3));
                    int e = e0 + 4*ty + i;
                    if (e < NEDGE){
                        int r = rS[e];
                        if (r != curr){
                            if (curr >= 0){
                                atomicAdd(mag + curr*SH + 4*tx + 0, s0);
                                atomicAdd(mag + curr*SH + 4*tx + 1, s1);
                                atomicAdd(mag + curr*SH + 4*tx + 2, s2);
                                atomicAdd(mag + curr*SH + 4*tx + 3, s3);
                            }
                            curr = r; s0 = s1 = s2 = s3 = 0.f;
                        }
                        s0 += m0; s1 += m1; s2 += m2; s3 += m3;
                    }
                }
                if (curr >= 0){
                    atomicAdd(mag + curr*SH + 4*tx + 0, s0);
                    atomicAdd(mag + curr*SH + 4*tx + 1, s1);
                    atomicAdd(mag + curr*SH + 4*tx + 2, s2);
                    atomicAdd(mag + curr*SH + 4*tx + 3, s3);
                }
            }
            __syncthreads();

            // GEMM2 core on tensor pipe: D = Mm @ C1
            mma_gemm_64(buf, C1pk + ((w >> 2) ? 2048 : 0), t);
            __syncthreads();

            // epilogue 2: t3 = silu(D + cb1); w = tanh(t3 . c2v); scatter coords
            {
                int tx = t & 15, ty = t >> 4;
                float wp[4];
                #pragma unroll
                for (int i = 0; i < 4; ++i){
                    float4 dv = *(const float4*)(buf + (4*ty+i)*SMM + 4*tx);
                    float z0 = silu_f(dv.x + cb1v[4*tx + 0]);
                    float z1 = silu_f(dv.y + cb1v[4*tx + 1]);
                    float z2 = silu_f(dv.z + cb1v[4*tx + 2]);
                    float z3 = silu_f(dv.w + cb1v[4*tx + 3]);
                    wp[i] = z0*c2v[4*tx+0] + z1*c2v[4*tx+1]
                          + z2*c2v[4*tx+2] + z3*c2v[4*tx+3];
                }
                #pragma unroll
                for (int m = 8; m >= 1; m >>= 1){
                    #pragma unroll
                    for (int i = 0; i < 4; ++i)
                        wp[i] += __shfl_xor_sync(0xffffffffu, wp[i], m, 16);
                }
                if (tx == 0){
                    #pragma unroll
                    for (int i = 0; i < 4; ++i){
                        int le = 4*ty + i, e = e0 + le;
                        if (e < NEDGE){
                            float ww = tanh_a(wp[i]);
                            int r = rS[e];
                            atomicAdd(aggx + r, cdx[le] * ww);
                            atomicAdd(aggy + r, cdy[le] * ww);
                        }
                    }
                }
            }
            __syncthreads();
        } // tiles

        // ---- x update (cnt == 19 exactly) ----
        if (t < NNODE){
            x0[t] += aggx[t] * (1.f/19.f);
            x1[t] += aggy[t] * (1.f/19.f);
        }

        // ---- node MLP pass1 via MMA: z1 = silu([h,m_agg] @ nw1 + nb1)  (K=128)
        float* z1 = buf;
        {
            float d[2][4];
            d[0][0]=0.f; d[0][1]=0.f; d[0][2]=0.f; d[0][3]=0.f;
            d[1][0]=0.f; d[1][1]=0.f; d[1][2]=0.f; d[1][3]=0.f;
            const float* Bpk = NW1pk_g + l*8192;
            const float* Ab1 = hS  + r0*SH + tig;
            const float* Ab2 = mag + r0*SH + tig;
            #pragma unroll
            for (int kt = 0; kt < 16; ++kt){
                const float* Ab = (kt < 8) ? Ab1 : Ab2;
                int kk = (kt < 8) ? kt : kt - 8;
                unsigned int a0 = __float_as_uint(Ab[kk*8]);
                unsigned int a1 = __float_as_uint(Ab[8*SH + kk*8]);
                unsigned int a2 = __float_as_uint(Ab[kk*8 + 4]);
                unsigned int a3 = __float_as_uint(Ab[8*SH + kk*8 + 4]);
                #pragma unroll
                for (int q = 0; q < 2; ++q){
                    int nt = nc*2 + q;
                    float2 bv = __ldg(reinterpret_cast<const float2*>(Bpk) + (kt*8 + nt)*32 + lane);
                    mma_tf32(d[q], a0, a1, a2, a3,
                             __float_as_uint(bv.x), __float_as_uint(bv.y));
                }
            }
            __syncthreads();   // mag/hS reads done; z1 (buf) write may alias garbage reads
            #pragma unroll
            for (int q = 0; q < 2; ++q){
                int c = nc*16 + q*8 + 2*tig;
                float bb0 = __ldg(nb1 + l*64 + c);
                float bb1 = __ldg(nb1 + l*64 + c + 1);
                if (r0 < NNODE){
                    z1[r0*SH + c]     = silu_f(d[q][0] + bb0);
                    z1[r0*SH + c + 1] = silu_f(d[q][1] + bb1);
                }
                if (r0 + 8 < NNODE){
                    z1[(r0+8)*SH + c]     = silu_f(d[q][2] + bb0);
                    z1[(r0+8)*SH + c + 1] = silu_f(d[q][3] + bb1);
                }
            }
        }
        __syncthreads();

        // ---- node MLP pass2 via MMA: h += z1 @ nw2 + nb2  (K=64) ----
        {
            float d[2][4];
            d[0][0]=0.f; d[0][1]=0.f; d[0][2]=0.f; d[0][3]=0.f;
            d[1][0]=0.f; d[1][1]=0.f; d[1][2]=0.f; d[1][3]=0.f;
            const float* Bpk = NW2pk_g + l*4096;
            const float* Ab = z1 + r0*SH + tig;
            #pragma unroll
            for (int kt = 0; kt < 8; ++kt){
                unsigned int a0 = __float_as_uint(Ab[kt*8]);
                unsigned int a1 = __float_as_uint(Ab[8*SH + kt*8]);
                unsigned int a2 = __float_as_uint(Ab[kt*8 + 4]);
                unsigned int a3 = __float_as_uint(Ab[8*SH + kt*8 + 4]);
                #pragma unroll
                for (int q = 0; q < 2; ++q){
                    int nt = nc*2 + q;
                    float2 bv = __ldg(reinterpret_cast<const float2*>(Bpk) + (kt*8 + nt)*32 + lane);
                    mma_tf32(d[q], a0, a1, a2, a3,
                             __float_as_uint(bv.x), __float_as_uint(bv.y));
                }
            }
            __syncthreads();   // z1 reads done before hS writes overlap next phases
            #pragma unroll
            for (int q = 0; q < 2; ++q){
                int c = nc*16 + q*8 + 2*tig;
                float bb0 = __ldg(nb2 + l*64 + c);
                float bb1 = __ldg(nb2 + l*64 + c + 1);
                if (r0 < NNODE){
                    hS[r0*SH + c]     += d[q][0] + bb0;
                    hS[r0*SH + c + 1] += d[q][1] + bb1;
                }
                if (r0 + 8 < NNODE){
                    hS[(r0+8)*SH + c]     += d[q][2] + bb0;
                    hS[(r0+8)*SH + c + 1] += d[q][3] + bb1;
                }
            }
        }
        __syncthreads();
    } // layers

    // ---- value head via MMA: z1 = tanh([xsq,h] @ fc1w + fc1b)  (K=64 + rank-1) ----
    float* z1 = buf;
    {
        float d[2][4];
        d[0][0]=0.f; d[0][1]=0.f; d[0][2]=0.f; d[0][3]=0.f;
        d[1][0]=0.f; d[1][1]=0.f; d[1][2]=0.f; d[1][3]=0.f;
        const float* Ab = hS + r0*SH + tig;
        #pragma unroll
        for (int kt = 0; kt < 8; ++kt){
            unsigned int a0 = __float_as_uint(Ab[kt*8]);
            unsigned int a1 = __float_as_uint(Ab[8*SH + kt*8]);
            unsigned int a2 = __float_as_uint(Ab[kt*8 + 4]);
            unsigned int a3 = __float_as_uint(Ab[8*SH + kt*8 + 4]);
            #pragma unroll
            for (int q = 0; q < 2; ++q){
                int nt = nc*2 + q;
                float2 bv = __ldg(reinterpret_cast<const float2*>(FC1pk_g) + (kt*8 + nt)*32 + lane);
                mma_tf32(d[q], a0, a1, a2, a3,
                         __float_as_uint(bv.x), __float_as_uint(bv.y));
            }
        }
        __syncthreads();
        float xsq0 = 0.f, xsq1 = 0.f;
        if (r0 < NNODE)     xsq0 = x0[r0]*x0[r0] + x1[r0]*x1[r0];
        if (r0 + 8 < NNODE) xsq1 = x0[r0+8]*x0[r0+8] + x1[r0+8]*x1[r0+8];
        #pragma unroll
        for (int q = 0; q < 2; ++q){
            int c = nc*16 + q*8 + 2*tig;
            float w00 = __ldg(fc1w + c),     w01 = __ldg(fc1w + c + 1);   // xsq row
            float bb0 = __ldg(fc1b + c),     bb1 = __ldg(fc1b + c + 1);
            if (r0 < NNODE){
                z1[r0*SH + c]     = tanh_a(fmaf(xsq0, w00, d[q][0] + bb0));
                z1[r0*SH + c + 1] = tanh_a(fmaf(xsq0, w01, d[q][1] + bb1));
            }
            if (r0 + 8 < NNODE){
                z1[(r0+8)*SH + c]     = tanh_a(fmaf(xsq1, w00, d[q][2] + bb0));
                z1[(r0+8)*SH + c + 1] = tanh_a(fmaf(xsq1, w01, d[q][3] + bb1));
            }
        }
    }
    __syncthreads();
    if (t < 32){
        float v = 0.f;
        if (t < NNODE){
            v = __ldg(fc2b);
            #pragma unroll 4
            for (int k4 = 0; k4 < 64; k4 += 4){
                float4 z = *(const float4*)(z1 + t*SH + k4);
                float4 wv = *(const float4*)(fc2w + k4);
                v = fmaf(z.x, wv.x, v); v = fmaf(z.y, wv.y, v);
                v = fmaf(z.z, wv.z, v); v = fmaf(z.w, wv.w, v);
            }
        }
        #pragma unroll
        for (int m = 16; m >= 1; m >>= 1) v += __shfl_xor_sync(0xffffffffu, v, m);
        if (t == 0) out[g] = v * (1.f / NNODE);
    }
    // rnn_states passthrough
    if (copy_rnn && t < 64) out[NB + g*64 + t] = rnn[g*64 + t];
}

extern "C" void kernel_launch(void* const* d_in, const int* in_sizes, int n_in,
                              void* d_out, int out_size)
{
    const float* obs   = (const float*)d_in[0];
    const float* rnn   = (const float*)d_in[1];
    // d_in[2] = masks (unused)
    const float* emb_w = (const float*)d_in[3];
    const float* emb_b = (const float*)d_in[4];
    const float* ew1   = (const float*)d_in[5];
    const float* eb1   = (const float*)d_in[6];
    const float* ew2   = (const float*)d_in[7];
    const float* eb2   = (const float*)d_in[8];
    const float* attw  = (const float*)d_in[9];
    const float* attb  = (const float*)d_in[10];
    const float* nw1   = (const float*)d_in[11];
    const float* nb1   = (const float*)d_in[12];
    const float* nw2   = (const float*)d_in[13];
    const float* nb2   = (const float*)d_in[14];
    const float* cw1   = (const float*)d_in[15];
    const float* cb1   = (const float*)d_in[16];
    const float* cw2   = (const float*)d_in[17];
    const float* fc1w  = (const float*)d_in[18];
    const float* fc1b  = (const float*)d_in[19];
    const float* fc2w  = (const float*)d_in[20];
    const float* fc2b  = (const float*)d_in[21];
    // d_in[22], d_in[23] = edge_row/edge_col (recomputed analytically)

    // pack fragment-ordered tf32 weights (graph-capturable kernel launches)
    pack_mma_kernel<<<48, 256>>>(ew2, cw1);
    pack_node_kernel<<<256, 256>>>(ew1, nw1, nw2, fc1w);

    const size_t smem_bytes = (size_t)SMEM_FLOATS * sizeof(float);
    cudaFuncSetAttribute(egnn_critic_kernel,
                         cudaFuncAttributeMaxDynamicSharedMemorySize,
                         (int)smem_bytes);

    int copy_rnn = (out_size >= NB + NB*HID) ? 1 : 0;

    egnn_critic_kernel<<<NB, BLK, smem_bytes>>>(
        obs, rnn, emb_w, emb_b, ew1, eb1, ew2, eb2, attw, attb,
        nw1, nb1, nw2, nb2, cw1, cb1, cw2, fc1w, fc1b, fc2w, fc2b,
        (float*)d_out, copy_rnn);
}